// round 1
// baseline (speedup 1.0000x reference)
#include <cuda_runtime.h>
#include <cuda_bf16.h>
#include <math.h>

// GPT-2 small forward: B=2, T=1024, L=12, C=1024, H=16, D=64, V=50257
#define Bc 2
#define Tc 1024
#define Cc 1024
#define Hc 16
#define Dc 64
#define Lc 12
#define Vc 50257
#define Mc (Bc*Tc)        // 2048 tokens

// -------------------- scratch (device globals; no allocation) --------------------
__device__ float g_x[Mc*Cc];        // residual stream
__device__ float g_h[Mc*Cc];        // layernorm output
__device__ float g_qkv[Mc*3*Cc];    // qkv
__device__ float g_att[Mc*Cc];      // attention output
__device__ float g_fc[Mc*4*Cc];     // mlp hidden

// -------------------- helpers --------------------
__device__ __forceinline__ float gelu_f(float x) {
    const float k = 0.7978845608028654f;
    float x3 = x*x*x;
    return 0.5f*x*(1.0f + tanhf(k*(x + 0.044715f*x3)));
}

template<int NT>
__device__ __forceinline__ float blockSum(float v, float* red) {
    #pragma unroll
    for (int o = 16; o > 0; o >>= 1) v += __shfl_xor_sync(0xffffffffu, v, o);
    int w = threadIdx.x >> 5;
    if ((threadIdx.x & 31) == 0) red[w] = v;
    __syncthreads();
    if (threadIdx.x == 0) {
        float s = 0.f;
        #pragma unroll
        for (int i = 0; i < NT/32; i++) s += red[i];
        red[0] = s;
    }
    __syncthreads();
    float r = red[0];
    __syncthreads();
    return r;
}

template<int NT>
__device__ __forceinline__ float blockMax(float v, float* red) {
    #pragma unroll
    for (int o = 16; o > 0; o >>= 1) v = fmaxf(v, __shfl_xor_sync(0xffffffffu, v, o));
    int w = threadIdx.x >> 5;
    if ((threadIdx.x & 31) == 0) red[w] = v;
    __syncthreads();
    if (threadIdx.x == 0) {
        float s = -1e30f;
        #pragma unroll
        for (int i = 0; i < NT/32; i++) s = fmaxf(s, red[i]);
        red[0] = s;
    }
    __syncthreads();
    float r = red[0];
    __syncthreads();
    return r;
}

// -------------------- embedding --------------------
__global__ void embed_kernel(const int* __restrict__ idx,
                             const float* __restrict__ wte,
                             const float* __restrict__ wpe) {
    int i = blockIdx.x*blockDim.x + threadIdx.x;
    if (i >= Mc*Cc) return;
    int row = i / Cc, c = i - row*Cc;
    int t = row & (Tc-1);
    g_x[i] = wte[(size_t)idx[row]*Cc + c] + wpe[t*Cc + c];
}

// -------------------- layernorm (one block per row, 256 threads) --------------------
__global__ void ln_kernel(const float* __restrict__ in, float* __restrict__ out,
                          const float* __restrict__ w, const float* __restrict__ b) {
    __shared__ float red[8];
    int row = blockIdx.x;
    const float* xr = in + (size_t)row*Cc;
    float v[4];
    float s = 0.f;
    #pragma unroll
    for (int i = 0; i < 4; i++) { v[i] = xr[threadIdx.x + i*256]; s += v[i]; }
    s = blockSum<256>(s, red);
    float mean = s * (1.0f/Cc);
    float vs = 0.f;
    #pragma unroll
    for (int i = 0; i < 4; i++) { float d = v[i]-mean; vs += d*d; }
    vs = blockSum<256>(vs, red);
    float rstd = rsqrtf(vs*(1.0f/Cc) + 1e-5f);
    float* orow = out + (size_t)row*Cc;
    #pragma unroll
    for (int i = 0; i < 4; i++) {
        int c = threadIdx.x + i*256;
        orow[c] = (v[i]-mean)*rstd*w[c] + b[c];
    }
}

// -------------------- tiled fp32 GEMM: C = A[M,K] @ B[K,N] (+bias)(gelu)(+resid) ----
// 64x64 tile, BK=16, 256 threads, 4x4 microtile.
__global__ void gemm_kernel(const float* __restrict__ A, const float* __restrict__ Bm,
                            const float* __restrict__ bias, const float* __restrict__ resid,
                            float* __restrict__ Cm, int M, int N, int K, int do_gelu) {
    __shared__ float As[16*68];   // [k][m], pad 68 (16B-aligned rows, low conflict)
    __shared__ float Bs[16*64];   // [k][n]
    int bn = blockIdx.x*64, bm = blockIdx.y*64;
    int tid = threadIdx.x;
    int tx = tid & 15, ty = tid >> 4;
    float acc[4][4];
    #pragma unroll
    for (int i = 0; i < 4; i++)
        #pragma unroll
        for (int j = 0; j < 4; j++) acc[i][j] = 0.f;

    for (int k0 = 0; k0 < K; k0 += 16) {
        #pragma unroll
        for (int i = 0; i < 4; i++) {
            int e = tid + i*256;
            int m = e >> 4, k = e & 15;
            As[k*68 + m] = A[(size_t)(bm+m)*K + k0 + k];
        }
        #pragma unroll
        for (int i = 0; i < 4; i++) {
            int e = tid + i*256;
            int k = e >> 6, n = e & 63;
            int gn = bn + n;
            Bs[k*64 + n] = (gn < N) ? Bm[(size_t)(k0+k)*N + gn] : 0.f;
        }
        __syncthreads();
        #pragma unroll
        for (int kk = 0; kk < 16; kk++) {
            float4 a4 = *reinterpret_cast<const float4*>(&As[kk*68 + ty*4]);
            float4 b4 = *reinterpret_cast<const float4*>(&Bs[kk*64 + tx*4]);
            float a[4] = {a4.x, a4.y, a4.z, a4.w};
            float bb[4] = {b4.x, b4.y, b4.z, b4.w};
            #pragma unroll
            for (int i = 0; i < 4; i++)
                #pragma unroll
                for (int j = 0; j < 4; j++)
                    acc[i][j] = fmaf(a[i], bb[j], acc[i][j]);
        }
        __syncthreads();
    }
    #pragma unroll
    for (int i = 0; i < 4; i++) {
        int m = bm + ty*4 + i;
        #pragma unroll
        for (int j = 0; j < 4; j++) {
            int n = bn + tx*4 + j;
            if (n < N) {
                float v = acc[i][j];
                if (bias)  v += bias[n];
                if (do_gelu) v = gelu_f(v);
                if (resid) v += resid[(size_t)m*N + n];
                Cm[(size_t)m*N + n] = v;
            }
        }
    }
}

// -------------------- attention: one block (128 thr) per (b,h,t) --------------------
__global__ void attn_kernel(const float* __restrict__ qkv, float* __restrict__ out) {
    __shared__ float qsm[64];
    __shared__ float ksm[128*65];
    __shared__ float scores[Tc];
    __shared__ float partial[64];
    __shared__ float red[4];

    int t = blockIdx.x, h = blockIdx.y, b = blockIdx.z;
    int tid = threadIdx.x;
    const float scale = 0.125f;  // 1/sqrt(64)

    const float* qrow = qkv + (size_t)(b*Tc + t)*3*Cc + h*Dc;
    if (tid < 64) qsm[tid] = qrow[tid];
    __syncthreads();

    int smax = t + 1;
    for (int s0 = 0; s0 < smax; s0 += 128) {
        int rows = min(128, smax - s0);
        for (int e = tid; e < rows*64; e += 128) {
            int sl = e >> 6, d = e & 63;
            ksm[sl*65 + d] = qkv[(size_t)(b*Tc + s0 + sl)*3*Cc + Cc + h*Dc + d];
        }
        __syncthreads();
        if (tid < rows) {
            float a = 0.f;
            #pragma unroll
            for (int d = 0; d < 64; d++) a = fmaf(qsm[d], ksm[tid*65 + d], a);
            scores[s0 + tid] = a * scale;
        }
        __syncthreads();
    }

    // softmax over scores[0..smax)
    float mx = -1e30f;
    for (int s = tid; s < smax; s += 128) mx = fmaxf(mx, scores[s]);
    mx = blockMax<128>(mx, red);
    float sum = 0.f;
    for (int s = tid; s < smax; s += 128) {
        float p = __expf(scores[s] - mx);
        scores[s] = p;
        sum += p;
    }
    sum = blockSum<128>(sum, red);
    float inv = 1.0f / sum;

    // out[d] = sum_s p[s] * v[s,d]; two halves of threads split s (coalesced over d)
    int d = tid & 63, half = tid >> 6;
    float acc = 0.f;
    for (int s = half; s < smax; s += 2)
        acc = fmaf(scores[s], qkv[(size_t)(b*Tc + s)*3*Cc + 2*Cc + h*Dc + d], acc);
    if (half == 1) partial[d] = acc;
    __syncthreads();
    if (half == 0)
        out[(size_t)(b*Tc + t)*Cc + h*Dc + d] = (acc + partial[d]) * inv;
}

// -------------------- launch --------------------
extern "C" void kernel_launch(void* const* d_in, const int* in_sizes, int n_in,
                              void* d_out, int out_size) {
    const int*   idx       = (const int*)  d_in[0];
    const float* wte       = (const float*)d_in[1];
    const float* wpe       = (const float*)d_in[2];
    const float* ln1_w     = (const float*)d_in[3];
    const float* ln1_b     = (const float*)d_in[4];
    const float* attn_w    = (const float*)d_in[5];
    const float* attn_b    = (const float*)d_in[6];
    const float* proj_w    = (const float*)d_in[7];
    const float* proj_b    = (const float*)d_in[8];
    const float* ln2_w     = (const float*)d_in[9];
    const float* ln2_b     = (const float*)d_in[10];
    const float* fc_w      = (const float*)d_in[11];
    const float* fc_b      = (const float*)d_in[12];
    const float* fcproj_w  = (const float*)d_in[13];
    const float* fcproj_b  = (const float*)d_in[14];
    const float* lnf_w     = (const float*)d_in[15];
    const float* lnf_b     = (const float*)d_in[16];
    const float* lm_head_w = (const float*)d_in[17];
    float* out = (float*)d_out;

    float *x, *h, *qkv, *att, *fc;
    cudaGetSymbolAddress((void**)&x,   g_x);
    cudaGetSymbolAddress((void**)&h,   g_h);
    cudaGetSymbolAddress((void**)&qkv, g_qkv);
    cudaGetSymbolAddress((void**)&att, g_att);
    cudaGetSymbolAddress((void**)&fc,  g_fc);

    // embedding
    embed_kernel<<<(Mc*Cc + 255)/256, 256>>>(idx, wte, wpe);

    dim3 gQKV(3*Cc/64, Mc/64);
    dim3 gPROJ(Cc/64, Mc/64);
    dim3 gFC(4*Cc/64, Mc/64);
    dim3 gHEAD((Vc + 63)/64, Mc/64);
    dim3 gATT(Tc, Hc, Bc);

    for (int l = 0; l < Lc; l++) {
        ln_kernel<<<Mc, 256>>>(x, h, ln1_w + l*Cc, ln1_b + l*Cc);
        gemm_kernel<<<gQKV, 256>>>(h, attn_w + (size_t)l*Cc*3*Cc, attn_b + (size_t)l*3*Cc,
                                   nullptr, qkv, Mc, 3*Cc, Cc, 0);
        attn_kernel<<<gATT, 128>>>(qkv, att);
        gemm_kernel<<<gPROJ, 256>>>(att, proj_w + (size_t)l*Cc*Cc, proj_b + (size_t)l*Cc,
                                    x, x, Mc, Cc, Cc, 0);
        ln_kernel<<<Mc, 256>>>(x, h, ln2_w + l*Cc, ln2_b + l*Cc);
        gemm_kernel<<<gFC, 256>>>(h, fc_w + (size_t)l*Cc*4*Cc, fc_b + (size_t)l*4*Cc,
                                  nullptr, fc, Mc, 4*Cc, Cc, 1);
        gemm_kernel<<<gPROJ, 256>>>(fc, fcproj_w + (size_t)l*4*Cc*Cc, fcproj_b + (size_t)l*Cc,
                                    x, x, Mc, Cc, 4*Cc, 0);
    }

    ln_kernel<<<Mc, 256>>>(x, h, lnf_w, lnf_b);
    gemm_kernel<<<gHEAD, 256>>>(h, lm_head_w, nullptr, nullptr, out, Mc, Vc, Cc, 0);
}

// round 3
// speedup vs baseline: 2.5995x; 2.5995x over previous
#include <cuda_runtime.h>
#include <cuda_bf16.h>
#include <math.h>

// GPT-2 small forward: B=2, T=1024, L=12, C=1024, H=16, D=64, V=50257
#define Bc 2
#define Tc 1024
#define Cc 1024
#define Hc 16
#define Dc 64
#define Lc 12
#define Vc 50257
#define Mc (Bc*Tc)        // 2048 tokens

// -------------------- scratch (device globals; no allocation) --------------------
__device__ float g_x[Mc*Cc];        // residual stream
__device__ float g_h[Mc*Cc];        // layernorm output
__device__ float g_qkv[Mc*3*Cc];    // qkv
__device__ float g_att[Mc*Cc];      // attention output
__device__ float g_fc[Mc*4*Cc];     // mlp hidden

// -------------------- helpers --------------------
__device__ __forceinline__ float gelu_f(float x) {
    const float k = 0.7978845608028654f;
    float x3 = x*x*x;
    return 0.5f*x*(1.0f + tanhf(k*(x + 0.044715f*x3)));
}

__device__ __forceinline__ unsigned f2tf32(float f) {
    unsigned r;
    asm("cvt.rna.tf32.f32 %0, %1;" : "=r"(r) : "f"(f));
    return r;
}

template<int NT>
__device__ __forceinline__ float blockSum(float v, float* red) {
    #pragma unroll
    for (int o = 16; o > 0; o >>= 1) v += __shfl_xor_sync(0xffffffffu, v, o);
    int w = threadIdx.x >> 5;
    if ((threadIdx.x & 31) == 0) red[w] = v;
    __syncthreads();
    if (threadIdx.x == 0) {
        float s = 0.f;
        #pragma unroll
        for (int i = 0; i < NT/32; i++) s += red[i];
        red[0] = s;
    }
    __syncthreads();
    float r = red[0];
    __syncthreads();
    return r;
}

// -------------------- embedding --------------------
__global__ void embed_kernel(const int* __restrict__ idx,
                             const float* __restrict__ wte,
                             const float* __restrict__ wpe) {
    int i = blockIdx.x*blockDim.x + threadIdx.x;
    if (i >= Mc*Cc) return;
    int row = i / Cc, c = i - row*Cc;
    int t = row & (Tc-1);
    g_x[i] = wte[(size_t)idx[row]*Cc + c] + wpe[t*Cc + c];
}

// -------------------- layernorm (one block per row, 256 threads) --------------------
__global__ void ln_kernel(const float* __restrict__ in, float* __restrict__ out,
                          const float* __restrict__ w, const float* __restrict__ b) {
    __shared__ float red[8];
    int row = blockIdx.x;
    const float* xr = in + (size_t)row*Cc;
    float v[4];
    float s = 0.f;
    #pragma unroll
    for (int i = 0; i < 4; i++) { v[i] = xr[threadIdx.x + i*256]; s += v[i]; }
    s = blockSum<256>(s, red);
    float mean = s * (1.0f/Cc);
    float vs = 0.f;
    #pragma unroll
    for (int i = 0; i < 4; i++) { float d = v[i]-mean; vs += d*d; }
    vs = blockSum<256>(vs, red);
    float rstd = rsqrtf(vs*(1.0f/Cc) + 1e-5f);
    float* orow = out + (size_t)row*Cc;
    #pragma unroll
    for (int i = 0; i < 4; i++) {
        int c = threadIdx.x + i*256;
        orow[c] = (v[i]-mean)*rstd*w[c] + b[c];
    }
}

// ==================== tf32 tensor-core GEMM ====================
// C[M,N] = A[M,K] @ B[K,N] (+bias)(gelu)(+resid)
// 128x128 block tile, BK=32, 256 threads (8 warps as 2x4), warp tile 64x32,
// mma.sync.m16n8k8 tf32, fp32 accumulate.
#define AS_STRIDE 36
#define BS_STRIDE 136

__device__ __forceinline__ void mma_tf32(float& c0, float& c1, float& c2, float& c3,
                                         unsigned a0, unsigned a1, unsigned a2, unsigned a3,
                                         unsigned b0, unsigned b1) {
    asm volatile(
        "mma.sync.aligned.m16n8k8.row.col.f32.tf32.tf32.f32 "
        "{%0,%1,%2,%3},{%4,%5,%6,%7},{%8,%9},{%0,%1,%2,%3};"
        : "+f"(c0), "+f"(c1), "+f"(c2), "+f"(c3)
        : "r"(a0), "r"(a1), "r"(a2), "r"(a3), "r"(b0), "r"(b1));
}

__global__ void __launch_bounds__(256)
gemm_tc(const float* __restrict__ A, const float* __restrict__ Bm,
        const float* __restrict__ bias, const float* __restrict__ resid,
        float* __restrict__ Cm, int M, int N, int K, int do_gelu) {
    __shared__ float As[128*AS_STRIDE];   // [row][k], stride 36 -> conflict-free frag loads
    __shared__ float Bs[32*BS_STRIDE];    // [k][n],  stride 136 -> conflict-free frag loads
    const int tid = threadIdx.x;
    const int lane = tid & 31, wid = tid >> 5;
    const int wm = wid >> 2, wn = wid & 3;       // 2 (M) x 4 (N) warps
    const int bm = blockIdx.y*128, bn = blockIdx.x*128;
    const bool n_vec4 = ((N & 3) == 0);          // row stride 16B-aligned?

    float acc[4][4][4];
    #pragma unroll
    for (int i = 0; i < 4; i++)
        #pragma unroll
        for (int j = 0; j < 4; j++)
            #pragma unroll
            for (int r = 0; r < 4; r++) acc[i][j][r] = 0.f;

    for (int k0 = 0; k0 < K; k0 += 32) {
        // load A tile 128x32 (row-major), convert to tf32
        #pragma unroll
        for (int i = 0; i < 4; i++) {
            int idx = tid + i*256;
            int row = idx >> 3, kq = (idx & 7) << 2;
            float4 v = *reinterpret_cast<const float4*>(A + (size_t)(bm+row)*K + k0 + kq);
            float4 w;
            w.x = __uint_as_float(f2tf32(v.x));
            w.y = __uint_as_float(f2tf32(v.y));
            w.z = __uint_as_float(f2tf32(v.z));
            w.w = __uint_as_float(f2tf32(v.w));
            *reinterpret_cast<float4*>(&As[row*AS_STRIDE + kq]) = w;
        }
        // load B tile 32x128 (row-major), convert to tf32.
        // float4 path only when N % 4 == 0 (alignment!); scalar-guarded otherwise.
        #pragma unroll
        for (int i = 0; i < 4; i++) {
            int idx = tid + i*256;
            int kr = idx >> 5, nq = (idx & 31) << 2;
            int gn = bn + nq;
            float4 v;
            if (n_vec4 && gn + 3 < N) {
                v = *reinterpret_cast<const float4*>(Bm + (size_t)(k0+kr)*N + gn);
            } else {
                const float* rowp = Bm + (size_t)(k0+kr)*N;
                v.x = (gn+0 < N) ? rowp[gn+0] : 0.f;
                v.y = (gn+1 < N) ? rowp[gn+1] : 0.f;
                v.z = (gn+2 < N) ? rowp[gn+2] : 0.f;
                v.w = (gn+3 < N) ? rowp[gn+3] : 0.f;
            }
            float4 w;
            w.x = __uint_as_float(f2tf32(v.x));
            w.y = __uint_as_float(f2tf32(v.y));
            w.z = __uint_as_float(f2tf32(v.z));
            w.w = __uint_as_float(f2tf32(v.w));
            *reinterpret_cast<float4*>(&Bs[kr*BS_STRIDE + nq]) = w;
        }
        __syncthreads();
        #pragma unroll
        for (int ks = 0; ks < 4; ks++) {
            unsigned a[4][4], b[4][2];
            int ar = wm*64 + (lane >> 2);
            int ac = ks*8 + (lane & 3);
            #pragma unroll
            for (int mt = 0; mt < 4; mt++) {
                const float* p = &As[(ar + mt*16)*AS_STRIDE + ac];
                a[mt][0] = __float_as_uint(p[0]);
                a[mt][1] = __float_as_uint(p[8*AS_STRIDE]);
                a[mt][2] = __float_as_uint(p[4]);
                a[mt][3] = __float_as_uint(p[8*AS_STRIDE + 4]);
            }
            int bk = ks*8 + (lane & 3);
            int bc = wn*32 + (lane >> 2);
            #pragma unroll
            for (int nt = 0; nt < 4; nt++) {
                const float* p = &Bs[bk*BS_STRIDE + bc + nt*8];
                b[nt][0] = __float_as_uint(p[0]);
                b[nt][1] = __float_as_uint(p[4*BS_STRIDE]);
            }
            #pragma unroll
            for (int mt = 0; mt < 4; mt++)
                #pragma unroll
                for (int nt = 0; nt < 4; nt++)
                    mma_tf32(acc[mt][nt][0], acc[mt][nt][1], acc[mt][nt][2], acc[mt][nt][3],
                             a[mt][0], a[mt][1], a[mt][2], a[mt][3],
                             b[nt][0], b[nt][1]);
        }
        __syncthreads();
    }

    // epilogue
    const int r0 = bm + wm*64 + (lane >> 2);
    const int c0 = bn + wn*32 + ((lane & 3) << 1);
    #pragma unroll
    for (int mt = 0; mt < 4; mt++) {
        #pragma unroll
        for (int nt = 0; nt < 4; nt++) {
            int cc = c0 + nt*8;
            #pragma unroll
            for (int half = 0; half < 2; half++) {
                int r = r0 + mt*16 + half*8;
                float v0 = acc[mt][nt][half*2 + 0];
                float v1 = acc[mt][nt][half*2 + 1];
                if (cc < N) {
                    float v = v0;
                    if (bias) v += bias[cc];
                    if (do_gelu) v = gelu_f(v);
                    if (resid) v += resid[(size_t)r*N + cc];
                    Cm[(size_t)r*N + cc] = v;
                }
                if (cc + 1 < N) {
                    float v = v1;
                    if (bias) v += bias[cc+1];
                    if (do_gelu) v = gelu_f(v);
                    if (resid) v += resid[(size_t)r*N + cc + 1];
                    Cm[(size_t)r*N + cc + 1] = v;
                }
            }
        }
    }
}

// ==================== tiled attention (flash-style, fp32) ====================
// block = (qtile of 64, head, batch), 256 threads.
// Each thread owns one query q = tid/4 and a strided d-quarter dq = tid%4
// (d = dq + 4*j, j=0..15). KV staged in smem in 32-row tiles; online softmax.
#define QT 64
#define KT 32
#define KPAD 68
#define SCPAD 36

__global__ void __launch_bounds__(256)
attn_tile_kernel(const float* __restrict__ qkv, float* __restrict__ out) {
    __shared__ float qsm[QT*KPAD];
    __shared__ float Ks[KT*KPAD];
    __shared__ float Vs[KT*KPAD];
    __shared__ float sc[QT*SCPAD];

    const int q0 = blockIdx.x * QT;
    const int h  = blockIdx.y;
    const int b  = blockIdx.z;
    const int tid = threadIdx.x;
    const int q  = tid >> 2;          // 0..63
    const int sq = tid & 3;           // 0..3
    const int qg = q0 + q;            // global query index
    const float scale = 0.125f;

    // load Q tile [64 x 64]
    #pragma unroll
    for (int i = 0; i < 4; i++) {
        int idx = tid + i*256;
        int row = idx >> 4, d = (idx & 15) << 2;
        float4 v = *reinterpret_cast<const float4*>(
            qkv + (size_t)(b*Tc + q0 + row)*3*Cc + h*Dc + d);
        *reinterpret_cast<float4*>(&qsm[row*KPAD + d]) = v;
    }

    float accv[16];
    #pragma unroll
    for (int j = 0; j < 16; j++) accv[j] = 0.f;
    float m_run = -1e30f, l_run = 0.f;

    const int ntiles = q0/KT + 2;
    for (int kt = 0; kt < ntiles; kt++) {
        const int kv0 = kt*KT;
        __syncthreads();
        // load K,V tiles [32 x 64]
        #pragma unroll
        for (int i = 0; i < 2; i++) {
            int idx = tid + i*256;
            int row = idx >> 4, d = (idx & 15) << 2;
            const float* base = qkv + (size_t)(b*Tc + kv0 + row)*3*Cc + h*Dc + d;
            *reinterpret_cast<float4*>(&Ks[row*KPAD + d]) =
                *reinterpret_cast<const float4*>(base + Cc);
            *reinterpret_cast<float4*>(&Vs[row*KPAD + d]) =
                *reinterpret_cast<const float4*>(base + 2*Cc);
        }
        __syncthreads();

        // scores: thread computes 8 scores at s = sq + 4*jj
        float sco[8];
        #pragma unroll
        for (int jj = 0; jj < 8; jj++) {
            int s = sq + 4*jj;
            float a = 0.f;
            #pragma unroll
            for (int k = 0; k < 64; k++)
                a = fmaf(qsm[q*KPAD + k], Ks[s*KPAD + k], a);
            sco[jj] = (kv0 + s <= qg) ? a*scale : -1e30f;
        }
        // online softmax (quad = 4 threads share query q)
        float mloc = sco[0];
        #pragma unroll
        for (int jj = 1; jj < 8; jj++) mloc = fmaxf(mloc, sco[jj]);
        mloc = fmaxf(mloc, __shfl_xor_sync(0xffffffffu, mloc, 1));
        mloc = fmaxf(mloc, __shfl_xor_sync(0xffffffffu, mloc, 2));
        float m_new = fmaxf(m_run, mloc);
        float alpha = __expf(m_run - m_new);
        float lloc = 0.f;
        #pragma unroll
        for (int jj = 0; jj < 8; jj++) {
            float p = __expf(sco[jj] - m_new);
            sc[q*SCPAD + sq + 4*jj] = p;
            lloc += p;
        }
        lloc += __shfl_xor_sync(0xffffffffu, lloc, 1);
        lloc += __shfl_xor_sync(0xffffffffu, lloc, 2);
        l_run = l_run*alpha + lloc;
        m_run = m_new;
        #pragma unroll
        for (int j = 0; j < 16; j++) accv[j] *= alpha;
        __syncwarp();
        // AV: acc[j] += p[s] * V[s][dq + 4j]
        #pragma unroll 4
        for (int s = 0; s < KT; s++) {
            float p = sc[q*SCPAD + s];
            #pragma unroll
            for (int j = 0; j < 16; j++)
                accv[j] = fmaf(p, Vs[s*KPAD + sq + 4*j], accv[j]);
        }
        __syncwarp();
    }

    float inv = 1.0f / l_run;
    float* orow = out + (size_t)(b*Tc + qg)*Cc + h*Dc;
    #pragma unroll
    for (int j = 0; j < 16; j++)
        orow[sq + 4*j] = accv[j] * inv;
}

// -------------------- launch --------------------
extern "C" void kernel_launch(void* const* d_in, const int* in_sizes, int n_in,
                              void* d_out, int out_size) {
    const int*   idx       = (const int*)  d_in[0];
    const float* wte       = (const float*)d_in[1];
    const float* wpe       = (const float*)d_in[2];
    const float* ln1_w     = (const float*)d_in[3];
    const float* ln1_b     = (const float*)d_in[4];
    const float* attn_w    = (const float*)d_in[5];
    const float* attn_b    = (const float*)d_in[6];
    const float* proj_w    = (const float*)d_in[7];
    const float* proj_b    = (const float*)d_in[8];
    const float* ln2_w     = (const float*)d_in[9];
    const float* ln2_b     = (const float*)d_in[10];
    const float* fc_w      = (const float*)d_in[11];
    const float* fc_b      = (const float*)d_in[12];
    const float* fcproj_w  = (const float*)d_in[13];
    const float* fcproj_b  = (const float*)d_in[14];
    const float* lnf_w     = (const float*)d_in[15];
    const float* lnf_b     = (const float*)d_in[16];
    const float* lm_head_w = (const float*)d_in[17];
    float* out = (float*)d_out;

    float *x, *h, *qkv, *att, *fc;
    cudaGetSymbolAddress((void**)&x,   g_x);
    cudaGetSymbolAddress((void**)&h,   g_h);
    cudaGetSymbolAddress((void**)&qkv, g_qkv);
    cudaGetSymbolAddress((void**)&att, g_att);
    cudaGetSymbolAddress((void**)&fc,  g_fc);

    embed_kernel<<<(Mc*Cc + 255)/256, 256>>>(idx, wte, wpe);

    dim3 gQKV(3*Cc/128, Mc/128);
    dim3 gPROJ(Cc/128, Mc/128);
    dim3 gFC(4*Cc/128, Mc/128);
    dim3 gHEAD((Vc + 127)/128, Mc/128);
    dim3 gATT(Tc/QT, Hc, Bc);

    for (int l = 0; l < Lc; l++) {
        ln_kernel<<<Mc, 256>>>(x, h, ln1_w + l*Cc, ln1_b + l*Cc);
        gemm_tc<<<gQKV, 256>>>(h, attn_w + (size_t)l*Cc*3*Cc, attn_b + (size_t)l*3*Cc,
                               nullptr, qkv, Mc, 3*Cc, Cc, 0);
        attn_tile_kernel<<<gATT, 256>>>(qkv, att);
        gemm_tc<<<gPROJ, 256>>>(att, proj_w + (size_t)l*Cc*Cc, proj_b + (size_t)l*Cc,
                                x, x, Mc, Cc, Cc, 0);
        ln_kernel<<<Mc, 256>>>(x, h, ln2_w + l*Cc, ln2_b + l*Cc);
        gemm_tc<<<gFC, 256>>>(h, fc_w + (size_t)l*Cc*4*Cc, fc_b + (size_t)l*4*Cc,
                              nullptr, fc, Mc, 4*Cc, Cc, 1);
        gemm_tc<<<gPROJ, 256>>>(fc, fcproj_w + (size_t)l*4*Cc*Cc, fcproj_b + (size_t)l*Cc,
                                x, x, Mc, Cc, 4*Cc, 0);
    }

    ln_kernel<<<Mc, 256>>>(x, h, lnf_w, lnf_b);
    gemm_tc<<<gHEAD, 256>>>(h, lm_head_w, nullptr, nullptr, out, Mc, Vc, Cc, 0);
}

// round 4
// speedup vs baseline: 3.0737x; 1.1824x over previous
#include <cuda_runtime.h>
#include <cuda_bf16.h>
#include <math.h>

// GPT-2 small forward: B=2, T=1024, L=12, C=1024, H=16, D=64, V=50257
#define Bc 2
#define Tc 1024
#define Cc 1024
#define Hc 16
#define Dc 64
#define Lc 12
#define Vc 50257
#define Mc (Bc*Tc)        // 2048 tokens

// -------------------- scratch (device globals; no allocation) --------------------
__device__ float g_x[Mc*Cc];        // residual stream
__device__ float g_h[Mc*Cc];        // layernorm output
__device__ float g_qkv[Mc*3*Cc];    // qkv
__device__ float g_att[Mc*Cc];      // attention output
__device__ float g_fc[Mc*4*Cc];     // mlp hidden

// -------------------- helpers --------------------
__device__ __forceinline__ float gelu_f(float x) {
    const float k = 0.7978845608028654f;
    float x3 = x*x*x;
    return 0.5f*x*(1.0f + tanhf(k*(x + 0.044715f*x3)));
}

__device__ __forceinline__ unsigned f2tf32(float f) {
    unsigned r;
    asm("cvt.rna.tf32.f32 %0, %1;" : "=r"(r) : "f"(f));
    return r;
}

template<int NT>
__device__ __forceinline__ float blockSum(float v, float* red) {
    #pragma unroll
    for (int o = 16; o > 0; o >>= 1) v += __shfl_xor_sync(0xffffffffu, v, o);
    int w = threadIdx.x >> 5;
    if ((threadIdx.x & 31) == 0) red[w] = v;
    __syncthreads();
    if (threadIdx.x == 0) {
        float s = 0.f;
        #pragma unroll
        for (int i = 0; i < NT/32; i++) s += red[i];
        red[0] = s;
    }
    __syncthreads();
    float r = red[0];
    __syncthreads();
    return r;
}

// -------------------- embedding --------------------
__global__ void embed_kernel(const int* __restrict__ idx,
                             const float* __restrict__ wte,
                             const float* __restrict__ wpe) {
    int i = blockIdx.x*blockDim.x + threadIdx.x;
    if (i >= Mc*Cc) return;
    int row = i / Cc, c = i - row*Cc;
    int t = row & (Tc-1);
    g_x[i] = wte[(size_t)idx[row]*Cc + c] + wpe[t*Cc + c];
}

// -------------------- layernorm (one block per row, 256 threads) --------------------
__global__ void ln_kernel(const float* __restrict__ in, float* __restrict__ out,
                          const float* __restrict__ w, const float* __restrict__ b) {
    __shared__ float red[8];
    int row = blockIdx.x;
    const float* xr = in + (size_t)row*Cc;
    float v[4];
    float s = 0.f;
    #pragma unroll
    for (int i = 0; i < 4; i++) { v[i] = xr[threadIdx.x + i*256]; s += v[i]; }
    s = blockSum<256>(s, red);
    float mean = s * (1.0f/Cc);
    float vs = 0.f;
    #pragma unroll
    for (int i = 0; i < 4; i++) { float d = v[i]-mean; vs += d*d; }
    vs = blockSum<256>(vs, red);
    float rstd = rsqrtf(vs*(1.0f/Cc) + 1e-5f);
    float* orow = out + (size_t)row*Cc;
    #pragma unroll
    for (int i = 0; i < 4; i++) {
        int c = threadIdx.x + i*256;
        orow[c] = (v[i]-mean)*rstd*w[c] + b[c];
    }
}

// ==================== tf32 tensor-core GEMM ====================
// C[M,N] = A[M,K] @ B[K,N] (+bias)(gelu)(+resid)
// 128x128 block tile, BK=32, 256 threads (8 warps as 2x4), warp tile 64x32,
// mma.sync.m16n8k8 tf32, fp32 accumulate.
#define AS_STRIDE 36
#define BS_STRIDE 136

__device__ __forceinline__ void mma_tf32(float& c0, float& c1, float& c2, float& c3,
                                         unsigned a0, unsigned a1, unsigned a2, unsigned a3,
                                         unsigned b0, unsigned b1) {
    asm volatile(
        "mma.sync.aligned.m16n8k8.row.col.f32.tf32.tf32.f32 "
        "{%0,%1,%2,%3},{%4,%5,%6,%7},{%8,%9},{%0,%1,%2,%3};"
        : "+f"(c0), "+f"(c1), "+f"(c2), "+f"(c3)
        : "r"(a0), "r"(a1), "r"(a2), "r"(a3), "r"(b0), "r"(b1));
}

__global__ void __launch_bounds__(256)
gemm_tc(const float* __restrict__ A, const float* __restrict__ Bm,
        const float* __restrict__ bias, const float* __restrict__ resid,
        float* __restrict__ Cm, int M, int N, int K, int do_gelu) {
    __shared__ float As[128*AS_STRIDE];   // [row][k], stride 36 -> conflict-free frag loads
    __shared__ float Bs[32*BS_STRIDE];    // [k][n],  stride 136 -> conflict-free frag loads
    const int tid = threadIdx.x;
    const int lane = tid & 31, wid = tid >> 5;
    const int wm = wid >> 2, wn = wid & 3;       // 2 (M) x 4 (N) warps
    const int bm = blockIdx.y*128, bn = blockIdx.x*128;
    const bool n_vec4 = ((N & 3) == 0);          // row stride 16B-aligned?

    float acc[4][4][4];
    #pragma unroll
    for (int i = 0; i < 4; i++)
        #pragma unroll
        for (int j = 0; j < 4; j++)
            #pragma unroll
            for (int r = 0; r < 4; r++) acc[i][j][r] = 0.f;

    for (int k0 = 0; k0 < K; k0 += 32) {
        // load A tile 128x32 (row-major), convert to tf32
        #pragma unroll
        for (int i = 0; i < 4; i++) {
            int idx = tid + i*256;
            int row = idx >> 3, kq = (idx & 7) << 2;
            float4 v = *reinterpret_cast<const float4*>(A + (size_t)(bm+row)*K + k0 + kq);
            float4 w;
            w.x = __uint_as_float(f2tf32(v.x));
            w.y = __uint_as_float(f2tf32(v.y));
            w.z = __uint_as_float(f2tf32(v.z));
            w.w = __uint_as_float(f2tf32(v.w));
            *reinterpret_cast<float4*>(&As[row*AS_STRIDE + kq]) = w;
        }
        // load B tile 32x128 (row-major), convert to tf32.
        // float4 path only when N % 4 == 0 (alignment!); scalar-guarded otherwise.
        #pragma unroll
        for (int i = 0; i < 4; i++) {
            int idx = tid + i*256;
            int kr = idx >> 5, nq = (idx & 31) << 2;
            int gn = bn + nq;
            float4 v;
            if (n_vec4 && gn + 3 < N) {
                v = *reinterpret_cast<const float4*>(Bm + (size_t)(k0+kr)*N + gn);
            } else {
                const float* rowp = Bm + (size_t)(k0+kr)*N;
                v.x = (gn+0 < N) ? rowp[gn+0] : 0.f;
                v.y = (gn+1 < N) ? rowp[gn+1] : 0.f;
                v.z = (gn+2 < N) ? rowp[gn+2] : 0.f;
                v.w = (gn+3 < N) ? rowp[gn+3] : 0.f;
            }
            float4 w;
            w.x = __uint_as_float(f2tf32(v.x));
            w.y = __uint_as_float(f2tf32(v.y));
            w.z = __uint_as_float(f2tf32(v.z));
            w.w = __uint_as_float(f2tf32(v.w));
            *reinterpret_cast<float4*>(&Bs[kr*BS_STRIDE + nq]) = w;
        }
        __syncthreads();
        #pragma unroll
        for (int ks = 0; ks < 4; ks++) {
            unsigned a[4][4], b[4][2];
            int ar = wm*64 + (lane >> 2);
            int ac = ks*8 + (lane & 3);
            #pragma unroll
            for (int mt = 0; mt < 4; mt++) {
                const float* p = &As[(ar + mt*16)*AS_STRIDE + ac];
                a[mt][0] = __float_as_uint(p[0]);
                a[mt][1] = __float_as_uint(p[8*AS_STRIDE]);
                a[mt][2] = __float_as_uint(p[4]);
                a[mt][3] = __float_as_uint(p[8*AS_STRIDE + 4]);
            }
            int bk = ks*8 + (lane & 3);
            int bc = wn*32 + (lane >> 2);
            #pragma unroll
            for (int nt = 0; nt < 4; nt++) {
                const float* p = &Bs[bk*BS_STRIDE + bc + nt*8];
                b[nt][0] = __float_as_uint(p[0]);
                b[nt][1] = __float_as_uint(p[4*BS_STRIDE]);
            }
            #pragma unroll
            for (int mt = 0; mt < 4; mt++)
                #pragma unroll
                for (int nt = 0; nt < 4; nt++)
                    mma_tf32(acc[mt][nt][0], acc[mt][nt][1], acc[mt][nt][2], acc[mt][nt][3],
                             a[mt][0], a[mt][1], a[mt][2], a[mt][3],
                             b[nt][0], b[nt][1]);
        }
        __syncthreads();
    }

    // epilogue
    const int r0 = bm + wm*64 + (lane >> 2);
    const int c0 = bn + wn*32 + ((lane & 3) << 1);
    #pragma unroll
    for (int mt = 0; mt < 4; mt++) {
        #pragma unroll
        for (int nt = 0; nt < 4; nt++) {
            int cc = c0 + nt*8;
            #pragma unroll
            for (int half = 0; half < 2; half++) {
                int r = r0 + mt*16 + half*8;
                float v0 = acc[mt][nt][half*2 + 0];
                float v1 = acc[mt][nt][half*2 + 1];
                if (cc < N) {
                    float v = v0;
                    if (bias) v += bias[cc];
                    if (do_gelu) v = gelu_f(v);
                    if (resid) v += resid[(size_t)r*N + cc];
                    Cm[(size_t)r*N + cc] = v;
                }
                if (cc + 1 < N) {
                    float v = v1;
                    if (bias) v += bias[cc+1];
                    if (do_gelu) v = gelu_f(v);
                    if (resid) v += resid[(size_t)r*N + cc + 1];
                    Cm[(size_t)r*N + cc + 1] = v;
                }
            }
        }
    }
}

// ==================== attention v3: register-tiled flash, fp32 ====================
// Block: 256 threads = 16(ty: q-groups) x 16(tx: s/d-groups); Q tile 64, KV tile 64.
// Q,K stored transposed in smem with XOR swizzle (col ^ (4*(row>>2))) so both the
// transpose STORES (2-way) and the d-major float4 READS (conflict-free) are cheap.
// Scores in a 4x4 register microtile; online softmax across tx via shfl; P via smem
// float4; PV as a second 4x4 microtile GEMM.
#define AQT 64
#define AKT 64
#define AST 68   // padded row stride (floats), multiple of 4 for float4 alignment

__global__ void __launch_bounds__(256)
attn_tile_kernel(const float* __restrict__ qkv, float* __restrict__ out) {
    extern __shared__ float sm[];
    float* qsmT = sm;                    // [64 d][AST]  (transposed, swizzled)
    float* ksT  = sm + 64*AST;           // [64 d][AST]  (transposed, swizzled)
    float* vsm  = sm + 2*64*AST;         // [64 s][AST]  (row-major)
    float* psm  = sm + 3*64*AST;         // [64 q][AST]  (row-major)

    const int q0 = blockIdx.x * AQT;
    const int h  = blockIdx.y;
    const int b  = blockIdx.z;
    const int tid = threadIdx.x;
    const int tx = tid & 15;             // s-group (scores) / d-group (PV)
    const int ty = tid >> 4;             // q-group
    const float scale = 0.125f;

    // ---- load Q tile transposed+swizzled, scale folded in ----
    #pragma unroll
    for (int i = 0; i < 4; i++) {
        int idx = tid + i*256;
        int q = idx >> 4, d4 = (idx & 15) << 2;   // d4 in {0,...,60}
        float4 v = *reinterpret_cast<const float4*>(
            qkv + (size_t)(b*Tc + q0 + q)*3*Cc + h*Dc + d4);
        int col = q ^ d4;                         // swizzle: c = 4*(row>>2) = d4
        qsmT[(d4+0)*AST + col] = v.x * scale;
        qsmT[(d4+1)*AST + col] = v.y * scale;
        qsmT[(d4+2)*AST + col] = v.z * scale;
        qsmT[(d4+3)*AST + col] = v.w * scale;
    }

    float o[4][4];
    #pragma unroll
    for (int i = 0; i < 4; i++)
        #pragma unroll
        for (int j = 0; j < 4; j++) o[i][j] = 0.f;
    float m_run[4], l_run[4];
    #pragma unroll
    for (int i = 0; i < 4; i++) { m_run[i] = -1e30f; l_run[i] = 0.f; }

    const int ntiles = q0/AKT + 1;
    for (int kt = 0; kt < ntiles; kt++) {
        const int kv0 = kt*AKT;
        __syncthreads();
        // ---- load K (transposed+swizzled) and V (row-major) ----
        #pragma unroll
        for (int i = 0; i < 4; i++) {
            int idx = tid + i*256;
            int s = idx >> 4, d4 = (idx & 15) << 2;
            const float* base = qkv + (size_t)(b*Tc + kv0 + s)*3*Cc + h*Dc + d4;
            float4 kv = *reinterpret_cast<const float4*>(base + Cc);
            int col = s ^ d4;
            ksT[(d4+0)*AST + col] = kv.x;
            ksT[(d4+1)*AST + col] = kv.y;
            ksT[(d4+2)*AST + col] = kv.z;
            ksT[(d4+3)*AST + col] = kv.w;
            *reinterpret_cast<float4*>(&vsm[s*AST + d4]) =
                *reinterpret_cast<const float4*>(base + 2*Cc);
        }
        __syncthreads();

        // ---- scores: 4x4 microtile over d ----
        float sco[4][4];
        #pragma unroll
        for (int i = 0; i < 4; i++)
            #pragma unroll
            for (int j = 0; j < 4; j++) sco[i][j] = 0.f;
        #pragma unroll 4
        for (int g = 0; g < 16; g++) {
            const float* qb = &qsmT[(4*g)*AST + ((ty*4) ^ (4*g))];
            const float* kb = &ksT [(4*g)*AST + ((tx*4) ^ (4*g))];
            #pragma unroll
            for (int dd = 0; dd < 4; dd++) {
                float4 q4 = *reinterpret_cast<const float4*>(qb + dd*AST);
                float4 k4 = *reinterpret_cast<const float4*>(kb + dd*AST);
                float qa[4] = {q4.x, q4.y, q4.z, q4.w};
                float ka[4] = {k4.x, k4.y, k4.z, k4.w};
                #pragma unroll
                for (int i = 0; i < 4; i++)
                    #pragma unroll
                    for (int j = 0; j < 4; j++)
                        sco[i][j] = fmaf(qa[i], ka[j], sco[i][j]);
            }
        }

        // ---- causal mask (diagonal tile only) ----
        if (kv0 == q0) {
            #pragma unroll
            for (int i = 0; i < 4; i++)
                #pragma unroll
                for (int j = 0; j < 4; j++)
                    if (tx*4 + j > ty*4 + i) sco[i][j] = -1e30f;
        }

        // ---- online softmax (reduce across 16 tx lanes, same half-warp) ----
        #pragma unroll
        for (int i = 0; i < 4; i++) {
            float mloc = fmaxf(fmaxf(sco[i][0], sco[i][1]), fmaxf(sco[i][2], sco[i][3]));
            #pragma unroll
            for (int off = 1; off < 16; off <<= 1)
                mloc = fmaxf(mloc, __shfl_xor_sync(0xffffffffu, mloc, off));
            float m_new = fmaxf(m_run[i], mloc);
            float alpha = __expf(m_run[i] - m_new);
            float p0 = __expf(sco[i][0] - m_new);
            float p1 = __expf(sco[i][1] - m_new);
            float p2 = __expf(sco[i][2] - m_new);
            float p3 = __expf(sco[i][3] - m_new);
            *reinterpret_cast<float4*>(&psm[(ty*4+i)*AST + tx*4]) =
                make_float4(p0, p1, p2, p3);
            float lloc = p0 + p1 + p2 + p3;
            #pragma unroll
            for (int off = 1; off < 16; off <<= 1)
                lloc += __shfl_xor_sync(0xffffffffu, lloc, off);
            l_run[i] = l_run[i]*alpha + lloc;
            m_run[i] = m_new;
            #pragma unroll
            for (int j = 0; j < 4; j++) o[i][j] *= alpha;
        }
        __syncwarp();

        // ---- PV: 4x4 microtile over s ----
        #pragma unroll 4
        for (int sg = 0; sg < 16; sg++) {
            float pr[4][4];
            #pragma unroll
            for (int i = 0; i < 4; i++) {
                float4 p4 = *reinterpret_cast<const float4*>(&psm[(ty*4+i)*AST + sg*4]);
                pr[i][0] = p4.x; pr[i][1] = p4.y; pr[i][2] = p4.z; pr[i][3] = p4.w;
            }
            #pragma unroll
            for (int k = 0; k < 4; k++) {
                float4 v4 = *reinterpret_cast<const float4*>(&vsm[(sg*4+k)*AST + tx*4]);
                float va[4] = {v4.x, v4.y, v4.z, v4.w};
                #pragma unroll
                for (int i = 0; i < 4; i++)
                    #pragma unroll
                    for (int j = 0; j < 4; j++)
                        o[i][j] = fmaf(pr[i][k], va[j], o[i][j]);
            }
        }
        __syncwarp();
    }

    // ---- write out ----
    #pragma unroll
    for (int i = 0; i < 4; i++) {
        float inv = 1.0f / l_run[i];
        float4 r = make_float4(o[i][0]*inv, o[i][1]*inv, o[i][2]*inv, o[i][3]*inv);
        *reinterpret_cast<float4*>(
            out + (size_t)(b*Tc + q0 + ty*4 + i)*Cc + h*Dc + tx*4) = r;
    }
}

// -------------------- launch --------------------
extern "C" void kernel_launch(void* const* d_in, const int* in_sizes, int n_in,
                              void* d_out, int out_size) {
    const int*   idx       = (const int*)  d_in[0];
    const float* wte       = (const float*)d_in[1];
    const float* wpe       = (const float*)d_in[2];
    const float* ln1_w     = (const float*)d_in[3];
    const float* ln1_b     = (const float*)d_in[4];
    const float* attn_w    = (const float*)d_in[5];
    const float* attn_b    = (const float*)d_in[6];
    const float* proj_w    = (const float*)d_in[7];
    const float* proj_b    = (const float*)d_in[8];
    const float* ln2_w     = (const float*)d_in[9];
    const float* ln2_b     = (const float*)d_in[10];
    const float* fc_w      = (const float*)d_in[11];
    const float* fc_b      = (const float*)d_in[12];
    const float* fcproj_w  = (const float*)d_in[13];
    const float* fcproj_b  = (const float*)d_in[14];
    const float* lnf_w     = (const float*)d_in[15];
    const float* lnf_b     = (const float*)d_in[16];
    const float* lm_head_w = (const float*)d_in[17];
    float* out = (float*)d_out;

    float *x, *h, *qkv, *att, *fc;
    cudaGetSymbolAddress((void**)&x,   g_x);
    cudaGetSymbolAddress((void**)&h,   g_h);
    cudaGetSymbolAddress((void**)&qkv, g_qkv);
    cudaGetSymbolAddress((void**)&att, g_att);
    cudaGetSymbolAddress((void**)&fc,  g_fc);

    const int attn_smem = 4*64*AST*sizeof(float);   // 69632 B
    cudaFuncSetAttribute(attn_tile_kernel,
                         cudaFuncAttributeMaxDynamicSharedMemorySize, attn_smem);

    embed_kernel<<<(Mc*Cc + 255)/256, 256>>>(idx, wte, wpe);

    dim3 gQKV(3*Cc/128, Mc/128);
    dim3 gPROJ(Cc/128, Mc/128);
    dim3 gFC(4*Cc/128, Mc/128);
    dim3 gHEAD((Vc + 127)/128, Mc/128);
    dim3 gATT(Tc/AQT, Hc, Bc);

    for (int l = 0; l < Lc; l++) {
        ln_kernel<<<Mc, 256>>>(x, h, ln1_w + l*Cc, ln1_b + l*Cc);
        gemm_tc<<<gQKV, 256>>>(h, attn_w + (size_t)l*Cc*3*Cc, attn_b + (size_t)l*3*Cc,
                               nullptr, qkv, Mc, 3*Cc, Cc, 0);
        attn_tile_kernel<<<gATT, 256, attn_smem>>>(qkv, att);
        gemm_tc<<<gPROJ, 256>>>(att, proj_w + (size_t)l*Cc*Cc, proj_b + (size_t)l*Cc,
                                x, x, Mc, Cc, Cc, 0);
        ln_kernel<<<Mc, 256>>>(x, h, ln2_w + l*Cc, ln2_b + l*Cc);
        gemm_tc<<<gFC, 256>>>(h, fc_w + (size_t)l*Cc*4*Cc, fc_b + (size_t)l*4*Cc,
                              nullptr, fc, Mc, 4*Cc, Cc, 1);
        gemm_tc<<<gPROJ, 256>>>(fc, fcproj_w + (size_t)l*4*Cc*Cc, fcproj_b + (size_t)l*Cc,
                                x, x, Mc, Cc, 4*Cc, 0);
    }

    ln_kernel<<<Mc, 256>>>(x, h, lnf_w, lnf_b);
    gemm_tc<<<gHEAD, 256>>>(h, lm_head_w, nullptr, nullptr, out, Mc, Vc, Cc, 0);
}

// round 6
// speedup vs baseline: 4.3111x; 1.4026x over previous
#include <cuda_runtime.h>
#include <cuda_bf16.h>
#include <math.h>

// GPT-2 small forward: B=2, T=1024, L=12, C=1024, H=16, D=64, V=50257
#define Bc 2
#define Tc 1024
#define Cc 1024
#define Hc 16
#define Dc 64
#define Lc 12
#define Vc 50257
#define Mc (Bc*Tc)        // 2048 tokens

// -------------------- scratch (device globals; no allocation) --------------------
__device__ float g_x[Mc*Cc];        // residual stream
__device__ float g_h[Mc*Cc];        // layernorm output
__device__ float g_qkv[Mc*3*Cc];    // qkv
__device__ float g_att[Mc*Cc];      // attention output
__device__ float g_fc[Mc*4*Cc];     // mlp hidden

// -------------------- helpers --------------------
__device__ __forceinline__ float gelu_f(float x) {
    const float k = 0.7978845608028654f;
    float x3 = x*x*x;
    return 0.5f*x*(1.0f + tanhf(k*(x + 0.044715f*x3)));
}

__device__ __forceinline__ unsigned f2tf32(float f) {
    unsigned r;
    asm("cvt.rna.tf32.f32 %0, %1;" : "=r"(r) : "f"(f));
    return r;
}

template<int NT>
__device__ __forceinline__ float blockSum(float v, float* red) {
    #pragma unroll
    for (int o = 16; o > 0; o >>= 1) v += __shfl_xor_sync(0xffffffffu, v, o);
    int w = threadIdx.x >> 5;
    if ((threadIdx.x & 31) == 0) red[w] = v;
    __syncthreads();
    if (threadIdx.x == 0) {
        float s = 0.f;
        #pragma unroll
        for (int i = 0; i < NT/32; i++) s += red[i];
        red[0] = s;
    }
    __syncthreads();
    float r = red[0];
    __syncthreads();
    return r;
}

// -------------------- embedding --------------------
__global__ void embed_kernel(const int* __restrict__ idx,
                             const float* __restrict__ wte,
                             const float* __restrict__ wpe) {
    int i = blockIdx.x*blockDim.x + threadIdx.x;
    if (i >= Mc*Cc) return;
    int row = i / Cc, c = i - row*Cc;
    int t = row & (Tc-1);
    g_x[i] = wte[(size_t)idx[row]*Cc + c] + wpe[t*Cc + c];
}

// -------------------- layernorm (one block per row, 256 threads) --------------------
__global__ void ln_kernel(const float* __restrict__ in, float* __restrict__ out,
                          const float* __restrict__ w, const float* __restrict__ b) {
    __shared__ float red[8];
    int row = blockIdx.x;
    const float* xr = in + (size_t)row*Cc;
    float v[4];
    float s = 0.f;
    #pragma unroll
    for (int i = 0; i < 4; i++) { v[i] = xr[threadIdx.x + i*256]; s += v[i]; }
    s = blockSum<256>(s, red);
    float mean = s * (1.0f/Cc);
    float vs = 0.f;
    #pragma unroll
    for (int i = 0; i < 4; i++) { float d = v[i]-mean; vs += d*d; }
    vs = blockSum<256>(vs, red);
    float rstd = rsqrtf(vs*(1.0f/Cc) + 1e-5f);
    float* orow = out + (size_t)row*Cc;
    #pragma unroll
    for (int i = 0; i < 4; i++) {
        int c = threadIdx.x + i*256;
        orow[c] = (v[i]-mean)*rstd*w[c] + b[c];
    }
}

// ==================== tf32 tensor-core GEMM (register-prefetch pipelined) ==========
// C[M,N] = A[M,K] @ B[K,N] (+bias)(gelu)(+resid)
// 128x128 block tile, BK=32, 256 threads (8 warps as 2x4), warp tile 64x32,
// mma.sync.m16n8k8 tf32, fp32 accumulate. Next tile prefetched into registers
// while the current smem tile is consumed, so gmem latency hides under the MMAs.
#define AS_STRIDE 36
#define BS_STRIDE 136

__device__ __forceinline__ void mma_tf32(float& c0, float& c1, float& c2, float& c3,
                                         unsigned a0, unsigned a1, unsigned a2, unsigned a3,
                                         unsigned b0, unsigned b1) {
    asm volatile(
        "mma.sync.aligned.m16n8k8.row.col.f32.tf32.tf32.f32 "
        "{%0,%1,%2,%3},{%4,%5,%6,%7},{%8,%9},{%0,%1,%2,%3};"
        : "+f"(c0), "+f"(c1), "+f"(c2), "+f"(c3)
        : "r"(a0), "r"(a1), "r"(a2), "r"(a3), "r"(b0), "r"(b1));
}

__global__ void __launch_bounds__(256, 2)
gemm_tc(const float* __restrict__ A, const float* __restrict__ Bm,
        const float* __restrict__ bias, const float* __restrict__ resid,
        float* __restrict__ Cm, int M, int N, int K, int do_gelu) {
    __shared__ float As[128*AS_STRIDE];   // [row][k], stride 36 -> conflict-free frag loads
    __shared__ float Bs[32*BS_STRIDE];    // [k][n],  stride 136 -> conflict-free frag loads
    const int tid = threadIdx.x;
    const int lane = tid & 31, wid = tid >> 5;
    const int wm = wid >> 2, wn = wid & 3;       // 2 (M) x 4 (N) warps
    const int bm = blockIdx.y*128, bn = blockIdx.x*128;
    const bool n_vec4 = ((N & 3) == 0);          // row stride 16B-aligned?

    // per-thread load coordinates (fixed across iters)
    const int a_row = tid >> 3, a_kq = (tid & 7) << 2;       // + i*32 rows
    const int b_kr  = tid >> 5, b_nq = (tid & 31) << 2;      // + i*8 k-rows

    float4 va[4], vb[4];

    auto loadA = [&](int k0) {
        #pragma unroll
        for (int i = 0; i < 4; i++)
            va[i] = *reinterpret_cast<const float4*>(
                A + (size_t)(bm + a_row + i*32)*K + k0 + a_kq);
    };
    auto loadB = [&](int k0) {
        int gn = bn + b_nq;
        #pragma unroll
        for (int i = 0; i < 4; i++) {
            int kr = b_kr + i*8;
            if (n_vec4 && gn + 3 < N) {
                vb[i] = *reinterpret_cast<const float4*>(Bm + (size_t)(k0+kr)*N + gn);
            } else {
                const float* rowp = Bm + (size_t)(k0+kr)*N;
                vb[i].x = (gn+0 < N) ? rowp[gn+0] : 0.f;
                vb[i].y = (gn+1 < N) ? rowp[gn+1] : 0.f;
                vb[i].z = (gn+2 < N) ? rowp[gn+2] : 0.f;
                vb[i].w = (gn+3 < N) ? rowp[gn+3] : 0.f;
            }
        }
    };
    auto storeTiles = [&]() {
        #pragma unroll
        for (int i = 0; i < 4; i++) {
            float4 w;
            w.x = __uint_as_float(f2tf32(va[i].x));
            w.y = __uint_as_float(f2tf32(va[i].y));
            w.z = __uint_as_float(f2tf32(va[i].z));
            w.w = __uint_as_float(f2tf32(va[i].w));
            *reinterpret_cast<float4*>(&As[(a_row + i*32)*AS_STRIDE + a_kq]) = w;
        }
        #pragma unroll
        for (int i = 0; i < 4; i++) {
            float4 w;
            w.x = __uint_as_float(f2tf32(vb[i].x));
            w.y = __uint_as_float(f2tf32(vb[i].y));
            w.z = __uint_as_float(f2tf32(vb[i].z));
            w.w = __uint_as_float(f2tf32(vb[i].w));
            *reinterpret_cast<float4*>(&Bs[(b_kr + i*8)*BS_STRIDE + b_nq]) = w;
        }
    };

    float acc[4][4][4];
    #pragma unroll
    for (int i = 0; i < 4; i++)
        #pragma unroll
        for (int j = 0; j < 4; j++)
            #pragma unroll
            for (int r = 0; r < 4; r++) acc[i][j][r] = 0.f;

    // prologue: first tile
    loadA(0); loadB(0);
    storeTiles();
    __syncthreads();

    for (int k0 = 0; k0 < K; k0 += 32) {
        const bool has_next = (k0 + 32 < K);
        if (has_next) { loadA(k0 + 32); loadB(k0 + 32); }  // LDGs in flight during MMAs

        #pragma unroll
        for (int ks = 0; ks < 4; ks++) {
            unsigned a[4][4], b[4][2];
            int ar = wm*64 + (lane >> 2);
            int ac = ks*8 + (lane & 3);
            #pragma unroll
            for (int mt = 0; mt < 4; mt++) {
                const float* p = &As[(ar + mt*16)*AS_STRIDE + ac];
                a[mt][0] = __float_as_uint(p[0]);
                a[mt][1] = __float_as_uint(p[8*AS_STRIDE]);
                a[mt][2] = __float_as_uint(p[4]);
                a[mt][3] = __float_as_uint(p[8*AS_STRIDE + 4]);
            }
            int bk = ks*8 + (lane & 3);
            int bc = wn*32 + (lane >> 2);
            #pragma unroll
            for (int nt = 0; nt < 4; nt++) {
                const float* p = &Bs[bk*BS_STRIDE + bc + nt*8];
                b[nt][0] = __float_as_uint(p[0]);
                b[nt][1] = __float_as_uint(p[4*BS_STRIDE]);
            }
            #pragma unroll
            for (int mt = 0; mt < 4; mt++)
                #pragma unroll
                for (int nt = 0; nt < 4; nt++)
                    mma_tf32(acc[mt][nt][0], acc[mt][nt][1], acc[mt][nt][2], acc[mt][nt][3],
                             a[mt][0], a[mt][1], a[mt][2], a[mt][3],
                             b[nt][0], b[nt][1]);
        }
        __syncthreads();          // everyone done reading this tile
        if (has_next) {
            storeTiles();         // overwrite with prefetched tile
            __syncthreads();      // stores visible
        }
    }

    // epilogue
    const int r0 = bm + wm*64 + (lane >> 2);
    const int c0 = bn + wn*32 + ((lane & 3) << 1);
    #pragma unroll
    for (int mt = 0; mt < 4; mt++) {
        #pragma unroll
        for (int nt = 0; nt < 4; nt++) {
            int cc = c0 + nt*8;
            #pragma unroll
            for (int half = 0; half < 2; half++) {
                int r = r0 + mt*16 + half*8;
                float v0 = acc[mt][nt][half*2 + 0];
                float v1 = acc[mt][nt][half*2 + 1];
                if (cc < N) {
                    float v = v0;
                    if (bias) v += bias[cc];
                    if (do_gelu) v = gelu_f(v);
                    if (resid) v += resid[(size_t)r*N + cc];
                    Cm[(size_t)r*N + cc] = v;
                }
                if (cc + 1 < N) {
                    float v = v1;
                    if (bias) v += bias[cc+1];
                    if (do_gelu) v = gelu_f(v);
                    if (resid) v += resid[(size_t)r*N + cc + 1];
                    Cm[(size_t)r*N + cc + 1] = v;
                }
            }
        }
    }
}

// ==================== attention: register-tiled flash, fp32 ====================
#define AQT 64
#define AKT 64
#define AST 68   // padded row stride (floats), multiple of 4 for float4 alignment

__global__ void __launch_bounds__(256)
attn_tile_kernel(const float* __restrict__ qkv, float* __restrict__ out) {
    extern __shared__ float sm[];
    float* qsmT = sm;                    // [64 d][AST]  (transposed, swizzled)
    float* ksT  = sm + 64*AST;           // [64 d][AST]  (transposed, swizzled)
    float* vsm  = sm + 2*64*AST;         // [64 s][AST]  (row-major)
    float* psm  = sm + 3*64*AST;         // [64 q][AST]  (row-major)

    const int q0 = blockIdx.x * AQT;
    const int h  = blockIdx.y;
    const int b  = blockIdx.z;
    const int tid = threadIdx.x;
    const int tx = tid & 15;             // s-group (scores) / d-group (PV)
    const int ty = tid >> 4;             // q-group
    const float scale = 0.125f;

    #pragma unroll
    for (int i = 0; i < 4; i++) {
        int idx = tid + i*256;
        int q = idx >> 4, d4 = (idx & 15) << 2;
        float4 v = *reinterpret_cast<const float4*>(
            qkv + (size_t)(b*Tc + q0 + q)*3*Cc + h*Dc + d4);
        int col = q ^ d4;
        qsmT[(d4+0)*AST + col] = v.x * scale;
        qsmT[(d4+1)*AST + col] = v.y * scale;
        qsmT[(d4+2)*AST + col] = v.z * scale;
        qsmT[(d4+3)*AST + col] = v.w * scale;
    }

    float o[4][4];
    #pragma unroll
    for (int i = 0; i < 4; i++)
        #pragma unroll
        for (int j = 0; j < 4; j++) o[i][j] = 0.f;
    float m_run[4], l_run[4];
    #pragma unroll
    for (int i = 0; i < 4; i++) { m_run[i] = -1e30f; l_run[i] = 0.f; }

    const int ntiles = q0/AKT + 1;
    for (int kt = 0; kt < ntiles; kt++) {
        const int kv0 = kt*AKT;
        __syncthreads();
        #pragma unroll
        for (int i = 0; i < 4; i++) {
            int idx = tid + i*256;
            int s = idx >> 4, d4 = (idx & 15) << 2;
            const float* base = qkv + (size_t)(b*Tc + kv0 + s)*3*Cc + h*Dc + d4;
            float4 kv = *reinterpret_cast<const float4*>(base + Cc);
            int col = s ^ d4;
            ksT[(d4+0)*AST + col] = kv.x;
            ksT[(d4+1)*AST + col] = kv.y;
            ksT[(d4+2)*AST + col] = kv.z;
            ksT[(d4+3)*AST + col] = kv.w;
            *reinterpret_cast<float4*>(&vsm[s*AST + d4]) =
                *reinterpret_cast<const float4*>(base + 2*Cc);
        }
        __syncthreads();

        float sco[4][4];
        #pragma unroll
        for (int i = 0; i < 4; i++)
            #pragma unroll
            for (int j = 0; j < 4; j++) sco[i][j] = 0.f;
        #pragma unroll 4
        for (int g = 0; g < 16; g++) {
            const float* qb = &qsmT[(4*g)*AST + ((ty*4) ^ (4*g))];
            const float* kb = &ksT [(4*g)*AST + ((tx*4) ^ (4*g))];
            #pragma unroll
            for (int dd = 0; dd < 4; dd++) {
                float4 q4 = *reinterpret_cast<const float4*>(qb + dd*AST);
                float4 k4 = *reinterpret_cast<const float4*>(kb + dd*AST);
                float qa[4] = {q4.x, q4.y, q4.z, q4.w};
                float ka[4] = {k4.x, k4.y, k4.z, k4.w};
                #pragma unroll
                for (int i = 0; i < 4; i++)
                    #pragma unroll
                    for (int j = 0; j < 4; j++)
                        sco[i][j] = fmaf(qa[i], ka[j], sco[i][j]);
            }
        }

        if (kv0 == q0) {
            #pragma unroll
            for (int i = 0; i < 4; i++)
                #pragma unroll
                for (int j = 0; j < 4; j++)
                    if (tx*4 + j > ty*4 + i) sco[i][j] = -1e30f;
        }

        #pragma unroll
        for (int i = 0; i < 4; i++) {
            float mloc = fmaxf(fmaxf(sco[i][0], sco[i][1]), fmaxf(sco[i][2], sco[i][3]));
            #pragma unroll
            for (int off = 1; off < 16; off <<= 1)
                mloc = fmaxf(mloc, __shfl_xor_sync(0xffffffffu, mloc, off));
            float m_new = fmaxf(m_run[i], mloc);
            float alpha = __expf(m_run[i] - m_new);
            float p0 = __expf(sco[i][0] - m_new);
            float p1 = __expf(sco[i][1] - m_new);
            float p2 = __expf(sco[i][2] - m_new);
            float p3 = __expf(sco[i][3] - m_new);
            *reinterpret_cast<float4*>(&psm[(ty*4+i)*AST + tx*4]) =
                make_float4(p0, p1, p2, p3);
            float lloc = p0 + p1 + p2 + p3;
            #pragma unroll
            for (int off = 1; off < 16; off <<= 1)
                lloc += __shfl_xor_sync(0xffffffffu, lloc, off);
            l_run[i] = l_run[i]*alpha + lloc;
            m_run[i] = m_new;
            #pragma unroll
            for (int j = 0; j < 4; j++) o[i][j] *= alpha;
        }
        __syncwarp();

        #pragma unroll 4
        for (int sg = 0; sg < 16; sg++) {
            float pr[4][4];
            #pragma unroll
            for (int i = 0; i < 4; i++) {
                float4 p4 = *reinterpret_cast<const float4*>(&psm[(ty*4+i)*AST + sg*4]);
                pr[i][0] = p4.x; pr[i][1] = p4.y; pr[i][2] = p4.z; pr[i][3] = p4.w;
            }
            #pragma unroll
            for (int k = 0; k < 4; k++) {
                float4 v4 = *reinterpret_cast<const float4*>(&vsm[(sg*4+k)*AST + tx*4]);
                float va[4] = {v4.x, v4.y, v4.z, v4.w};
                #pragma unroll
                for (int i = 0; i < 4; i++)
                    #pragma unroll
                    for (int j = 0; j < 4; j++)
                        o[i][j] = fmaf(pr[i][k], va[j], o[i][j]);
            }
        }
        __syncwarp();
    }

    #pragma unroll
    for (int i = 0; i < 4; i++) {
        float inv = 1.0f / l_run[i];
        float4 r = make_float4(o[i][0]*inv, o[i][1]*inv, o[i][2]*inv, o[i][3]*inv);
        *reinterpret_cast<float4*>(
            out + (size_t)(b*Tc + q0 + ty*4 + i)*Cc + h*Dc + tx*4) = r;
    }
}

// -------------------- launch --------------------
extern "C" void kernel_launch(void* const* d_in, const int* in_sizes, int n_in,
                              void* d_out, int out_size) {
    const int*   idx       = (const int*)  d_in[0];
    const float* wte       = (const float*)d_in[1];
    const float* wpe       = (const float*)d_in[2];
    const float* ln1_w     = (const float*)d_in[3];
    const float* ln1_b     = (const float*)d_in[4];
    const float* attn_w    = (const float*)d_in[5];
    const float* attn_b    = (const float*)d_in[6];
    const float* proj_w    = (const float*)d_in[7];
    const float* proj_b    = (const float*)d_in[8];
    const float* ln2_w     = (const float*)d_in[9];
    const float* ln2_b     = (const float*)d_in[10];
    const float* fc_w      = (const float*)d_in[11];
    const float* fc_b      = (const float*)d_in[12];
    const float* fcproj_w  = (const float*)d_in[13];
    const float* fcproj_b  = (const float*)d_in[14];
    const float* lnf_w     = (const float*)d_in[15];
    const float* lnf_b     = (const float*)d_in[16];
    const float* lm_head_w = (const float*)d_in[17];
    float* out = (float*)d_out;

    float *x, *h, *qkv, *att, *fc;
    cudaGetSymbolAddress((void**)&x,   g_x);
    cudaGetSymbolAddress((void**)&h,   g_h);
    cudaGetSymbolAddress((void**)&qkv, g_qkv);
    cudaGetSymbolAddress((void**)&att, g_att);
    cudaGetSymbolAddress((void**)&fc,  g_fc);

    const int attn_smem = 4*64*AST*sizeof(float);   // 69632 B
    cudaFuncSetAttribute(attn_tile_kernel,
                         cudaFuncAttributeMaxDynamicSharedMemorySize, attn_smem);

    embed_kernel<<<(Mc*Cc + 255)/256, 256>>>(idx, wte, wpe);

    dim3 gQKV(3*Cc/128, Mc/128);
    dim3 gPROJ(Cc/128, Mc/128);
    dim3 gFC(4*Cc/128, Mc/128);
    dim3 gHEAD((Vc + 127)/128, Mc/128);
    dim3 gATT(Tc/AQT, Hc, Bc);

    for (int l = 0; l < Lc; l++) {
        ln_kernel<<<Mc, 256>>>(x, h, ln1_w + l*Cc, ln1_b + l*Cc);
        gemm_tc<<<gQKV, 256>>>(h, attn_w + (size_t)l*Cc*3*Cc, attn_b + (size_t)l*3*Cc,
                               nullptr, qkv, Mc, 3*Cc, Cc, 0);
        attn_tile_kernel<<<gATT, 256, attn_smem>>>(qkv, att);
        gemm_tc<<<gPROJ, 256>>>(att, proj_w + (size_t)l*Cc*Cc, proj_b + (size_t)l*Cc,
                                x, x, Mc, Cc, Cc, 0);
        ln_kernel<<<Mc, 256>>>(x, h, ln2_w + l*Cc, ln2_b + l*Cc);
        gemm_tc<<<gFC, 256>>>(h, fc_w + (size_t)l*Cc*4*Cc, fc_b + (size_t)l*4*Cc,
                              nullptr, fc, Mc, 4*Cc, Cc, 1);
        gemm_tc<<<gPROJ, 256>>>(fc, fcproj_w + (size_t)l*4*Cc*Cc, fcproj_b + (size_t)l*Cc,
                                x, x, Mc, Cc, 4*Cc, 0);
    }

    ln_kernel<<<Mc, 256>>>(x, h, lnf_w, lnf_b);
    gemm_tc<<<gHEAD, 256>>>(h, lm_head_w, nullptr, nullptr, out, Mc, Vc, Cc, 0);
}

// round 10
// speedup vs baseline: 5.2791x; 1.2245x over previous
#include <cuda_runtime.h>
#include <cuda_fp16.h>
#include <cuda_bf16.h>
#include <math.h>
#include <stdint.h>

// GPT-2 small forward: B=2, T=1024, L=12, C=1024, H=16, D=64, V=50257
#define Bc 2
#define Tc 1024
#define Cc 1024
#define Hc 16
#define Dc 64
#define Lc 12
#define Vc 50257
#define Mc (Bc*Tc)        // 2048 tokens

// -------------------- scratch (device globals; no allocation) --------------------
__device__ float g_x[Mc*Cc];        // residual stream
__device__ float g_h[Mc*Cc];        // layernorm output
__device__ float g_qkv[Mc*3*Cc];    // qkv
__device__ float g_att[Mc*Cc];      // attention output
__device__ float g_fc[Mc*4*Cc];     // mlp hidden

// -------------------- helpers --------------------
__device__ __forceinline__ float gelu_f(float x) {
    const float k = 0.7978845608028654f;
    float x3 = x*x*x;
    return 0.5f*x*(1.0f + tanhf(k*(x + 0.044715f*x3)));
}

__device__ __forceinline__ uint32_t smem_u32(const void* p) {
    uint32_t a;
    asm("{ .reg .u64 t; cvta.to.shared.u64 t, %1; cvt.u32.u64 %0, t; }" : "=r"(a) : "l"(p));
    return a;
}

template<int NT>
__device__ __forceinline__ float blockSum(float v, float* red) {
    #pragma unroll
    for (int o = 16; o > 0; o >>= 1) v += __shfl_xor_sync(0xffffffffu, v, o);
    int w = threadIdx.x >> 5;
    if ((threadIdx.x & 31) == 0) red[w] = v;
    __syncthreads();
    if (threadIdx.x == 0) {
        float s = 0.f;
        #pragma unroll
        for (int i = 0; i < NT/32; i++) s += red[i];
        red[0] = s;
    }
    __syncthreads();
    float r = red[0];
    __syncthreads();
    return r;
}

// -------------------- embedding --------------------
__global__ void embed_kernel(const int* __restrict__ idx,
                             const float* __restrict__ wte,
                             const float* __restrict__ wpe) {
    int i = blockIdx.x*blockDim.x + threadIdx.x;
    if (i >= Mc*Cc) return;
    int row = i / Cc, c = i - row*Cc;
    int t = row & (Tc-1);
    g_x[i] = wte[(size_t)idx[row]*Cc + c] + wpe[t*Cc + c];
}

// -------------------- layernorm (one block per row, 256 threads) --------------------
__global__ void ln_kernel(const float* __restrict__ in, float* __restrict__ out,
                          const float* __restrict__ w, const float* __restrict__ b) {
    __shared__ float red[8];
    int row = blockIdx.x;
    const float* xr = in + (size_t)row*Cc;
    float v[4];
    float s = 0.f;
    #pragma unroll
    for (int i = 0; i < 4; i++) { v[i] = xr[threadIdx.x + i*256]; s += v[i]; }
    s = blockSum<256>(s, red);
    float mean = s * (1.0f/Cc);
    float vs = 0.f;
    #pragma unroll
    for (int i = 0; i < 4; i++) { float d = v[i]-mean; vs += d*d; }
    vs = blockSum<256>(vs, red);
    float rstd = rsqrtf(vs*(1.0f/Cc) + 1e-5f);
    float* orow = out + (size_t)row*Cc;
    #pragma unroll
    for (int i = 0; i < 4; i++) {
        int c = threadIdx.x + i*256;
        orow[c] = (v[i]-mean)*rstd*w[c] + b[c];
    }
}

// ==================== fp16 tensor-core GEMM (register-prefetch pipelined) ==========
// C[M,N] = A[M,K] @ B[K,N] (+bias)(gelu)(+resid)
// 128x128 block tile, BK=32, 256 threads (8 warps as 2x4), warp tile 64x32,
// mma.sync.m16n8k16.f32.f16.f16.f32, ldmatrix fragment loads.
#define ASH 40     // A smem row stride in halves (80 B)
#define BSH 136    // B smem row stride in halves (272 B)

__device__ __forceinline__ void mma_f16(float& c0, float& c1, float& c2, float& c3,
                                        unsigned a0, unsigned a1, unsigned a2, unsigned a3,
                                        unsigned b0, unsigned b1) {
    asm volatile(
        "mma.sync.aligned.m16n8k16.row.col.f32.f16.f16.f32 "
        "{%0,%1,%2,%3},{%4,%5,%6,%7},{%8,%9},{%0,%1,%2,%3};"
        : "+f"(c0), "+f"(c1), "+f"(c2), "+f"(c3)
        : "r"(a0), "r"(a1), "r"(a2), "r"(a3), "r"(b0), "r"(b1));
}

__device__ __forceinline__ void ldsm_x4(unsigned& r0, unsigned& r1, unsigned& r2, unsigned& r3,
                                        uint32_t addr) {
    asm volatile("ldmatrix.sync.aligned.m8n8.x4.shared.b16 {%0,%1,%2,%3}, [%4];"
                 : "=r"(r0), "=r"(r1), "=r"(r2), "=r"(r3) : "r"(addr));
}

__device__ __forceinline__ void ldsm_x2t(unsigned& r0, unsigned& r1, uint32_t addr) {
    asm volatile("ldmatrix.sync.aligned.m8n8.x2.trans.shared.b16 {%0,%1}, [%2];"
                 : "=r"(r0), "=r"(r1) : "r"(addr));
}

__device__ __forceinline__ unsigned pack_h2(float lo, float hi) {
    __half2 h = __floats2half2_rn(lo, hi);
    return *reinterpret_cast<unsigned*>(&h);
}

__global__ void __launch_bounds__(256, 2)
gemm_hm(const float* __restrict__ A, const float* __restrict__ Bm,
        const float* __restrict__ bias, const float* __restrict__ resid,
        float* __restrict__ Cm, int M, int N, int K, int do_gelu) {
    __shared__ __half As[128*ASH];   // [m][k]
    __shared__ __half Bs[32*BSH];    // [k][n]
    const int tid = threadIdx.x;
    const int lane = tid & 31, wid = tid >> 5;
    const int wm = wid >> 2, wn = wid & 3;       // 2 (M) x 4 (N) warps
    const int bm = blockIdx.y*128, bn = blockIdx.x*128;
    const bool n_vec4 = ((N & 3) == 0);

    // per-thread load coordinates
    const int a_row = tid >> 3, a_kq = (tid & 7) << 2;       // + i*32 rows
    const int b_kr  = tid >> 5, b_nq = (tid & 31) << 2;      // + i*8 k-rows

    float4 va[4], vb[4];

    auto loadA = [&](int k0) {
        #pragma unroll
        for (int i = 0; i < 4; i++)
            va[i] = *reinterpret_cast<const float4*>(
                A + (size_t)(bm + a_row + i*32)*K + k0 + a_kq);
    };
    auto loadB = [&](int k0) {
        int gn = bn + b_nq;
        #pragma unroll
        for (int i = 0; i < 4; i++) {
            int kr = b_kr + i*8;
            if (n_vec4 && gn + 3 < N) {
                vb[i] = *reinterpret_cast<const float4*>(Bm + (size_t)(k0+kr)*N + gn);
            } else {
                const float* rowp = Bm + (size_t)(k0+kr)*N;
                vb[i].x = (gn+0 < N) ? rowp[gn+0] : 0.f;
                vb[i].y = (gn+1 < N) ? rowp[gn+1] : 0.f;
                vb[i].z = (gn+2 < N) ? rowp[gn+2] : 0.f;
                vb[i].w = (gn+3 < N) ? rowp[gn+3] : 0.f;
            }
        }
    };
    auto storeTiles = [&]() {
        #pragma unroll
        for (int i = 0; i < 4; i++) {
            uint2 p;
            p.x = pack_h2(va[i].x, va[i].y);
            p.y = pack_h2(va[i].z, va[i].w);
            *reinterpret_cast<uint2*>(&As[(a_row + i*32)*ASH + a_kq]) = p;
        }
        #pragma unroll
        for (int i = 0; i < 4; i++) {
            uint2 p;
            p.x = pack_h2(vb[i].x, vb[i].y);
            p.y = pack_h2(vb[i].z, vb[i].w);
            *reinterpret_cast<uint2*>(&Bs[(b_kr + i*8)*BSH + b_nq]) = p;
        }
    };

    float acc[4][4][4];
    #pragma unroll
    for (int i = 0; i < 4; i++)
        #pragma unroll
        for (int j = 0; j < 4; j++)
            #pragma unroll
            for (int r = 0; r < 4; r++) acc[i][j][r] = 0.f;

    loadA(0); loadB(0);
    storeTiles();
    __syncthreads();

    // ldmatrix base addresses (depend only on lane)
    const int a_lm_row = wm*64 + (lane & 15);
    const int a_lm_k   = (lane >> 4) << 3;       // 0 or 8
    const int b_lm_k   = lane & 15;
    const int b_lm_n   = wn*32;

    for (int k0 = 0; k0 < K; k0 += 32) {
        const bool has_next = (k0 + 32 < K);
        if (has_next) { loadA(k0 + 32); loadB(k0 + 32); }

        #pragma unroll
        for (int ks = 0; ks < 2; ks++) {         // two k16 chunks
            unsigned a[4][4], b[4][2];
            #pragma unroll
            for (int mt = 0; mt < 4; mt++) {
                uint32_t addr = smem_u32(&As[(a_lm_row + mt*16)*ASH + ks*16 + a_lm_k]);
                ldsm_x4(a[mt][0], a[mt][1], a[mt][2], a[mt][3], addr);
            }
            #pragma unroll
            for (int nt = 0; nt < 4; nt++) {
                uint32_t addr = smem_u32(&Bs[(ks*16 + b_lm_k)*BSH + b_lm_n + nt*8]);
                ldsm_x2t(b[nt][0], b[nt][1], addr);
            }
            #pragma unroll
            for (int mt = 0; mt < 4; mt++)
                #pragma unroll
                for (int nt = 0; nt < 4; nt++)
                    mma_f16(acc[mt][nt][0], acc[mt][nt][1], acc[mt][nt][2], acc[mt][nt][3],
                            a[mt][0], a[mt][1], a[mt][2], a[mt][3],
                            b[nt][0], b[nt][1]);
        }
        __syncthreads();
        if (has_next) {
            storeTiles();
            __syncthreads();
        }
    }

    // epilogue (m16n8 accumulator layout: c0/c1 row lane/4, cols 2*(lane&3)+{0,1}; c2/c3 +8 rows)
    const int r0 = bm + wm*64 + (lane >> 2);
    const int c0 = bn + wn*32 + ((lane & 3) << 1);
    #pragma unroll
    for (int mt = 0; mt < 4; mt++) {
        #pragma unroll
        for (int nt = 0; nt < 4; nt++) {
            int cc = c0 + nt*8;
            #pragma unroll
            for (int half = 0; half < 2; half++) {
                int r = r0 + mt*16 + half*8;
                float v0 = acc[mt][nt][half*2 + 0];
                float v1 = acc[mt][nt][half*2 + 1];
                if (cc < N) {
                    float v = v0;
                    if (bias) v += bias[cc];
                    if (do_gelu) v = gelu_f(v);
                    if (resid) v += resid[(size_t)r*N + cc];
                    Cm[(size_t)r*N + cc] = v;
                }
                if (cc + 1 < N) {
                    float v = v1;
                    if (bias) v += bias[cc+1];
                    if (do_gelu) v = gelu_f(v);
                    if (resid) v += resid[(size_t)r*N + cc + 1];
                    Cm[(size_t)r*N + cc + 1] = v;
                }
            }
        }
    }
}

// ==================== attention: register-tiled flash, fp32 ====================
#define AQT 64
#define AKT 64
#define AST 68

__global__ void __launch_bounds__(256)
attn_tile_kernel(const float* __restrict__ qkv, float* __restrict__ out) {
    extern __shared__ float sm[];
    float* qsmT = sm;
    float* ksT  = sm + 64*AST;
    float* vsm  = sm + 2*64*AST;
    float* psm  = sm + 3*64*AST;

    const int q0 = blockIdx.x * AQT;
    const int h  = blockIdx.y;
    const int b  = blockIdx.z;
    const int tid = threadIdx.x;
    const int tx = tid & 15;
    const int ty = tid >> 4;
    const float scale = 0.125f;

    #pragma unroll
    for (int i = 0; i < 4; i++) {
        int idx = tid + i*256;
        int q = idx >> 4, d4 = (idx & 15) << 2;
        float4 v = *reinterpret_cast<const float4*>(
            qkv + (size_t)(b*Tc + q0 + q)*3*Cc + h*Dc + d4);
        int col = q ^ d4;
        qsmT[(d4+0)*AST + col] = v.x * scale;
        qsmT[(d4+1)*AST + col] = v.y * scale;
        qsmT[(d4+2)*AST + col] = v.z * scale;
        qsmT[(d4+3)*AST + col] = v.w * scale;
    }

    float o[4][4];
    #pragma unroll
    for (int i = 0; i < 4; i++)
        #pragma unroll
        for (int j = 0; j < 4; j++) o[i][j] = 0.f;
    float m_run[4], l_run[4];
    #pragma unroll
    for (int i = 0; i < 4; i++) { m_run[i] = -1e30f; l_run[i] = 0.f; }

    const int ntiles = q0/AKT + 1;
    for (int kt = 0; kt < ntiles; kt++) {
        const int kv0 = kt*AKT;
        __syncthreads();
        #pragma unroll
        for (int i = 0; i < 4; i++) {
            int idx = tid + i*256;
            int s = idx >> 4, d4 = (idx & 15) << 2;
            const float* base = qkv + (size_t)(b*Tc + kv0 + s)*3*Cc + h*Dc + d4;
            float4 kv = *reinterpret_cast<const float4*>(base + Cc);
            int col = s ^ d4;
            ksT[(d4+0)*AST + col] = kv.x;
            ksT[(d4+1)*AST + col] = kv.y;
            ksT[(d4+2)*AST + col] = kv.z;
            ksT[(d4+3)*AST + col] = kv.w;
            *reinterpret_cast<float4*>(&vsm[s*AST + d4]) =
                *reinterpret_cast<const float4*>(base + 2*Cc);
        }
        __syncthreads();

        float sco[4][4];
        #pragma unroll
        for (int i = 0; i < 4; i++)
            #pragma unroll
            for (int j = 0; j < 4; j++) sco[i][j] = 0.f;
        #pragma unroll 4
        for (int g = 0; g < 16; g++) {
            const float* qb = &qsmT[(4*g)*AST + ((ty*4) ^ (4*g))];
            const float* kb = &ksT [(4*g)*AST + ((tx*4) ^ (4*g))];
            #pragma unroll
            for (int dd = 0; dd < 4; dd++) {
                float4 q4 = *reinterpret_cast<const float4*>(qb + dd*AST);
                float4 k4 = *reinterpret_cast<const float4*>(kb + dd*AST);
                float qa[4] = {q4.x, q4.y, q4.z, q4.w};
                float ka[4] = {k4.x, k4.y, k4.z, k4.w};
                #pragma unroll
                for (int i = 0; i < 4; i++)
                    #pragma unroll
                    for (int j = 0; j < 4; j++)
                        sco[i][j] = fmaf(qa[i], ka[j], sco[i][j]);
            }
        }

        if (kv0 == q0) {
            #pragma unroll
            for (int i = 0; i < 4; i++)
                #pragma unroll
                for (int j = 0; j < 4; j++)
                    if (tx*4 + j > ty*4 + i) sco[i][j] = -1e30f;
        }

        #pragma unroll
        for (int i = 0; i < 4; i++) {
            float mloc = fmaxf(fmaxf(sco[i][0], sco[i][1]), fmaxf(sco[i][2], sco[i][3]));
            #pragma unroll
            for (int off = 1; off < 16; off <<= 1)
                mloc = fmaxf(mloc, __shfl_xor_sync(0xffffffffu, mloc, off));
            float m_new = fmaxf(m_run[i], mloc);
            float alpha = __expf(m_run[i] - m_new);
            float p0 = __expf(sco[i][0] - m_new);
            float p1 = __expf(sco[i][1] - m_new);
            float p2 = __expf(sco[i][2] - m_new);
            float p3 = __expf(sco[i][3] - m_new);
            *reinterpret_cast<float4*>(&psm[(ty*4+i)*AST + tx*4]) =
                make_float4(p0, p1, p2, p3);
            float lloc = p0 + p1 + p2 + p3;
            #pragma unroll
            for (int off = 1; off < 16; off <<= 1)
                lloc += __shfl_xor_sync(0xffffffffu, lloc, off);
            l_run[i] = l_run[i]*alpha + lloc;
            m_run[i] = m_new;
            #pragma unroll
            for (int j = 0; j < 4; j++) o[i][j] *= alpha;
        }
        __syncwarp();

        #pragma unroll 4
        for (int sg = 0; sg < 16; sg++) {
            float pr[4][4];
            #pragma unroll
            for (int i = 0; i < 4; i++) {
                float4 p4 = *reinterpret_cast<const float4*>(&psm[(ty*4+i)*AST + sg*4]);
                pr[i][0] = p4.x; pr[i][1] = p4.y; pr[i][2] = p4.z; pr[i][3] = p4.w;
            }
            #pragma unroll
            for (int k = 0; k < 4; k++) {
                float4 v4 = *reinterpret_cast<const float4*>(&vsm[(sg*4+k)*AST + tx*4]);
                float va[4] = {v4.x, v4.y, v4.z, v4.w};
                #pragma unroll
                for (int i = 0; i < 4; i++)
                    #pragma unroll
                    for (int j = 0; j < 4; j++)
                        o[i][j] = fmaf(pr[i][k], va[j], o[i][j]);
            }
        }
        __syncwarp();
    }

    #pragma unroll
    for (int i = 0; i < 4; i++) {
        float inv = 1.0f / l_run[i];
        float4 r = make_float4(o[i][0]*inv, o[i][1]*inv, o[i][2]*inv, o[i][3]*inv);
        *reinterpret_cast<float4*>(
            out + (size_t)(b*Tc + q0 + ty*4 + i)*Cc + h*Dc + tx*4) = r;
    }
}

// -------------------- launch --------------------
extern "C" void kernel_launch(void* const* d_in, const int* in_sizes, int n_in,
                              void* d_out, int out_size) {
    const int*   idx       = (const int*)  d_in[0];
    const float* wte       = (const float*)d_in[1];
    const float* wpe       = (const float*)d_in[2];
    const float* ln1_w     = (const float*)d_in[3];
    const float* ln1_b     = (const float*)d_in[4];
    const float* attn_w    = (const float*)d_in[5];
    const float* attn_b    = (const float*)d_in[6];
    const float* proj_w    = (const float*)d_in[7];
    const float* proj_b    = (const float*)d_in[8];
    const float* ln2_w     = (const float*)d_in[9];
    const float* ln2_b     = (const float*)d_in[10];
    const float* fc_w      = (const float*)d_in[11];
    const float* fc_b      = (const float*)d_in[12];
    const float* fcproj_w  = (const float*)d_in[13];
    const float* fcproj_b  = (const float*)d_in[14];
    const float* lnf_w     = (const float*)d_in[15];
    const float* lnf_b     = (const float*)d_in[16];
    const float* lm_head_w = (const float*)d_in[17];
    float* out = (float*)d_out;

    float *x, *h, *qkv, *att, *fc;
    cudaGetSymbolAddress((void**)&x,   g_x);
    cudaGetSymbolAddress((void**)&h,   g_h);
    cudaGetSymbolAddress((void**)&qkv, g_qkv);
    cudaGetSymbolAddress((void**)&att, g_att);
    cudaGetSymbolAddress((void**)&fc,  g_fc);

    const int attn_smem = 4*64*AST*sizeof(float);
    cudaFuncSetAttribute(attn_tile_kernel,
                         cudaFuncAttributeMaxDynamicSharedMemorySize, attn_smem);

    embed_kernel<<<(Mc*Cc + 255)/256, 256>>>(idx, wte, wpe);

    dim3 gQKV(3*Cc/128, Mc/128);
    dim3 gPROJ(Cc/128, Mc/128);
    dim3 gFC(4*Cc/128, Mc/128);
    dim3 gHEAD((Vc + 127)/128, Mc/128);
    dim3 gATT(Tc/AQT, Hc, Bc);

    for (int l = 0; l < Lc; l++) {
        ln_kernel<<<Mc, 256>>>(x, h, ln1_w + l*Cc, ln1_b + l*Cc);
        gemm_hm<<<gQKV, 256>>>(h, attn_w + (size_t)l*Cc*3*Cc, attn_b + (size_t)l*3*Cc,
                               nullptr, qkv, Mc, 3*Cc, Cc, 0);
        attn_tile_kernel<<<gATT, 256, attn_smem>>>(qkv, att);
        gemm_hm<<<gPROJ, 256>>>(att, proj_w + (size_t)l*Cc*Cc, proj_b + (size_t)l*Cc,
                                x, x, Mc, Cc, Cc, 0);
        ln_kernel<<<Mc, 256>>>(x, h, ln2_w + l*Cc, ln2_b + l*Cc);
        gemm_hm<<<gFC, 256>>>(h, fc_w + (size_t)l*Cc*4*Cc, fc_b + (size_t)l*4*Cc,
                              nullptr, fc, Mc, 4*Cc, Cc, 1);
        gemm_hm<<<gPROJ, 256>>>(fc, fcproj_w + (size_t)l*4*Cc*Cc, fcproj_b + (size_t)l*Cc,
                                x, x, Mc, Cc, 4*Cc, 0);
    }

    ln_kernel<<<Mc, 256>>>(x, h, lnf_w, lnf_b);
    gemm_hm<<<gHEAD, 256>>>(h, lm_head_w, nullptr, nullptr, out, Mc, Vc, Cc, 0);
}

// round 12
// speedup vs baseline: 7.2581x; 1.3749x over previous
#include <cuda_runtime.h>
#include <cuda_fp16.h>
#include <math.h>
#include <stdint.h>

// GPT-2 small forward: B=2, T=1024, L=12, C=1024, H=16, D=64, V=50257
#define Bc 2
#define Tc 1024
#define Cc 1024
#define Hc 16
#define Dc 64
#define Lc 12
#define Vc 50257
#define Vpad 50304        // 393*128, multiple of 128
#define Mc (Bc*Tc)        // 2048 tokens

// -------------------- scratch (device globals; no allocation) --------------------
__device__ float g_x[Mc*Cc];          // residual stream
__device__ float g_h[Mc*Cc];          // layernorm output
__device__ float g_att[Mc*Cc];        // attention output (fp32)
__device__ float g_fc[Mc*4*Cc];       // mlp hidden
__device__ __half g_qkv_h[Mc*3*Cc];   // qkv in fp16 (written by qkv GEMM)
// fp16 weights (converted once per launch)
__device__ __half g_wqkv_h[Lc*Cc*3*Cc];
__device__ __half g_wproj_h[Lc*Cc*Cc];
__device__ __half g_wfc_h[Lc*Cc*4*Cc];
__device__ __half g_wfcp_h[Lc*4*Cc*Cc];
__device__ __half g_wlm_h[Cc*Vpad];

// -------------------- helpers --------------------
__device__ __forceinline__ float gelu_f(float x) {
    const float k = 0.7978845608028654f;
    float x3 = x*x*x;
    return 0.5f*x*(1.0f + tanhf(k*(x + 0.044715f*x3)));
}

__device__ __forceinline__ uint32_t smem_u32(const void* p) {
    uint32_t a;
    asm("{ .reg .u64 t; cvta.to.shared.u64 t, %1; cvt.u32.u64 %0, t; }" : "=r"(a) : "l"(p));
    return a;
}

template<int NT>
__device__ __forceinline__ float blockSum(float v, float* red) {
    #pragma unroll
    for (int o = 16; o > 0; o >>= 1) v += __shfl_xor_sync(0xffffffffu, v, o);
    int w = threadIdx.x >> 5;
    if ((threadIdx.x & 31) == 0) red[w] = v;
    __syncthreads();
    if (threadIdx.x == 0) {
        float s = 0.f;
        #pragma unroll
        for (int i = 0; i < NT/32; i++) s += red[i];
        red[0] = s;
    }
    __syncthreads();
    float r = red[0];
    __syncthreads();
    return r;
}

// -------------------- weight conversion fp32 -> fp16 (padded) --------------------
__global__ void cvt_w_kernel(const float* __restrict__ src, __half* __restrict__ dst,
                             int total, int N, int Npad) {
    int i = blockIdx.x*256 + threadIdx.x;
    if (i >= total) return;
    int row = i / Npad, n = i - row*Npad;
    dst[i] = (n < N) ? __float2half(src[(size_t)row*N + n]) : __float2half(0.f);
}

// -------------------- embedding --------------------
__global__ void embed_kernel(const int* __restrict__ idx,
                             const float* __restrict__ wte,
                             const float* __restrict__ wpe) {
    int i = blockIdx.x*blockDim.x + threadIdx.x;
    if (i >= Mc*Cc) return;
    int row = i / Cc, c = i - row*Cc;
    int t = row & (Tc-1);
    g_x[i] = wte[(size_t)idx[row]*Cc + c] + wpe[t*Cc + c];
}

// -------------------- layernorm --------------------
__global__ void ln_kernel(const float* __restrict__ in, float* __restrict__ out,
                          const float* __restrict__ w, const float* __restrict__ b) {
    __shared__ float red[8];
    int row = blockIdx.x;
    const float* xr = in + (size_t)row*Cc;
    float v[4];
    float s = 0.f;
    #pragma unroll
    for (int i = 0; i < 4; i++) { v[i] = xr[threadIdx.x + i*256]; s += v[i]; }
    s = blockSum<256>(s, red);
    float mean = s * (1.0f/Cc);
    float vs = 0.f;
    #pragma unroll
    for (int i = 0; i < 4; i++) { float d = v[i]-mean; vs += d*d; }
    vs = blockSum<256>(vs, red);
    float rstd = rsqrtf(vs*(1.0f/Cc) + 1e-5f);
    float* orow = out + (size_t)row*Cc;
    #pragma unroll
    for (int i = 0; i < 4; i++) {
        int c = threadIdx.x + i*256;
        orow[c] = (v[i]-mean)*rstd*w[c] + b[c];
    }
}

// ==================== fp16 tensor-core GEMM (half B, prefetch pipelined) ==========
#define ASH 40     // A smem row stride in halves
#define BSH 136    // B smem row stride in halves

__device__ __forceinline__ void mma_f16(float& c0, float& c1, float& c2, float& c3,
                                        unsigned a0, unsigned a1, unsigned a2, unsigned a3,
                                        unsigned b0, unsigned b1) {
    asm volatile(
        "mma.sync.aligned.m16n8k16.row.col.f32.f16.f16.f32 "
        "{%0,%1,%2,%3},{%4,%5,%6,%7},{%8,%9},{%0,%1,%2,%3};"
        : "+f"(c0), "+f"(c1), "+f"(c2), "+f"(c3)
        : "r"(a0), "r"(a1), "r"(a2), "r"(a3), "r"(b0), "r"(b1));
}

__device__ __forceinline__ void ldsm_x4(unsigned& r0, unsigned& r1, unsigned& r2, unsigned& r3,
                                        uint32_t addr) {
    asm volatile("ldmatrix.sync.aligned.m8n8.x4.shared.b16 {%0,%1,%2,%3}, [%4];"
                 : "=r"(r0), "=r"(r1), "=r"(r2), "=r"(r3) : "r"(addr));
}
__device__ __forceinline__ void ldsm_x2(unsigned& r0, unsigned& r1, uint32_t addr) {
    asm volatile("ldmatrix.sync.aligned.m8n8.x2.shared.b16 {%0,%1}, [%2];"
                 : "=r"(r0), "=r"(r1) : "r"(addr));
}
__device__ __forceinline__ void ldsm_x2t(unsigned& r0, unsigned& r1, uint32_t addr) {
    asm volatile("ldmatrix.sync.aligned.m8n8.x2.trans.shared.b16 {%0,%1}, [%2];"
                 : "=r"(r0), "=r"(r1) : "r"(addr));
}
__device__ __forceinline__ unsigned pack_h2(float lo, float hi) {
    __half2 h = __floats2half2_rn(lo, hi);
    return *reinterpret_cast<unsigned*>(&h);
}

__global__ void __launch_bounds__(256, 2)
gemm_hm(const float* __restrict__ A, const __half* __restrict__ Bh, int ldb,
        const float* __restrict__ bias, const float* __restrict__ resid,
        float* __restrict__ Cm, __half* __restrict__ Ch,
        int M, int N, int K, int do_gelu) {
    __shared__ __half As[128*ASH];   // [m][k]
    __shared__ __half Bs[32*BSH];    // [k][n]
    const int tid = threadIdx.x;
    const int lane = tid & 31, wid = tid >> 5;
    const int wm = wid >> 2, wn = wid & 3;
    const int bm = blockIdx.y*128, bn = blockIdx.x*128;

    const int a_row = tid >> 3, a_kq = (tid & 7) << 2;
    const int b_k  = tid >> 4, b_n8 = (tid & 15) << 3;       // + i*16 k-rows

    float4 va[4];
    uint4  vbh[2];

    auto loadA = [&](int k0) {
        #pragma unroll
        for (int i = 0; i < 4; i++)
            va[i] = *reinterpret_cast<const float4*>(
                A + (size_t)(bm + a_row + i*32)*K + k0 + a_kq);
    };
    auto loadB = [&](int k0) {
        #pragma unroll
        for (int i = 0; i < 2; i++)
            vbh[i] = *reinterpret_cast<const uint4*>(
                Bh + (size_t)(k0 + b_k + i*16)*ldb + bn + b_n8);
    };
    auto storeTiles = [&]() {
        #pragma unroll
        for (int i = 0; i < 4; i++) {
            uint2 p;
            p.x = pack_h2(va[i].x, va[i].y);
            p.y = pack_h2(va[i].z, va[i].w);
            *reinterpret_cast<uint2*>(&As[(a_row + i*32)*ASH + a_kq]) = p;
        }
        #pragma unroll
        for (int i = 0; i < 2; i++)
            *reinterpret_cast<uint4*>(&Bs[(b_k + i*16)*BSH + b_n8]) = vbh[i];
    };

    float acc[4][4][4];
    #pragma unroll
    for (int i = 0; i < 4; i++)
        #pragma unroll
        for (int j = 0; j < 4; j++)
            #pragma unroll
            for (int r = 0; r < 4; r++) acc[i][j][r] = 0.f;

    loadA(0); loadB(0);
    storeTiles();
    __syncthreads();

    const int a_lm_row = wm*64 + (lane & 15);
    const int a_lm_k   = (lane >> 4) << 3;
    const int b_lm_k   = lane & 15;
    const int b_lm_n   = wn*32;

    for (int k0 = 0; k0 < K; k0 += 32) {
        const bool has_next = (k0 + 32 < K);
        if (has_next) { loadA(k0 + 32); loadB(k0 + 32); }

        #pragma unroll
        for (int ks = 0; ks < 2; ks++) {
            unsigned a[4][4], b[4][2];
            #pragma unroll
            for (int mt = 0; mt < 4; mt++) {
                uint32_t addr = smem_u32(&As[(a_lm_row + mt*16)*ASH + ks*16 + a_lm_k]);
                ldsm_x4(a[mt][0], a[mt][1], a[mt][2], a[mt][3], addr);
            }
            #pragma unroll
            for (int nt = 0; nt < 4; nt++) {
                uint32_t addr = smem_u32(&Bs[(ks*16 + b_lm_k)*BSH + b_lm_n + nt*8]);
                ldsm_x2t(b[nt][0], b[nt][1], addr);
            }
            #pragma unroll
            for (int mt = 0; mt < 4; mt++)
                #pragma unroll
                for (int nt = 0; nt < 4; nt++)
                    mma_f16(acc[mt][nt][0], acc[mt][nt][1], acc[mt][nt][2], acc[mt][nt][3],
                            a[mt][0], a[mt][1], a[mt][2], a[mt][3],
                            b[nt][0], b[nt][1]);
        }
        __syncthreads();
        if (has_next) {
            storeTiles();
            __syncthreads();
        }
    }

    const int r0 = bm + wm*64 + (lane >> 2);
    const int c0 = bn + wn*32 + ((lane & 3) << 1);
    #pragma unroll
    for (int mt = 0; mt < 4; mt++) {
        #pragma unroll
        for (int nt = 0; nt < 4; nt++) {
            int cc = c0 + nt*8;
            #pragma unroll
            for (int half = 0; half < 2; half++) {
                int r = r0 + mt*16 + half*8;
                #pragma unroll
                for (int j = 0; j < 2; j++) {
                    int c = cc + j;
                    if (c < N) {
                        float v = acc[mt][nt][half*2 + j];
                        if (bias) v += bias[c];
                        if (do_gelu) v = gelu_f(v);
                        size_t o = (size_t)r*N + c;
                        if (resid) v += resid[o];
                        if (Cm) Cm[o] = v;
                        if (Ch) Ch[o] = __float2half(v);
                    }
                }
            }
        }
    }
}

// ==================== fp16 tensor-core flash attention ====================
// Block: 128 threads = 4 warps; each warp owns 16 q-rows; q-tile 64, kv-tile 64.
// QK^T and PV via mma.m16n8k16; FA2 fragment softmax (quad shfl).
#define ATS 72   // smem row stride in halves

__global__ void __launch_bounds__(128)
attn_mma_kernel(const __half* __restrict__ qkvh, float* __restrict__ out) {
    __shared__ __half Qs[64*ATS];
    __shared__ __half Ks[64*ATS];
    __shared__ __half Vs[64*ATS];

    const int q0 = blockIdx.x * 64;
    const int h  = blockIdx.y;
    const int b  = blockIdx.z;
    const int tid = threadIdx.x;
    const int lane = tid & 31, w = tid >> 5;
    const int qw = q0 + w*16;           // warp's q base
    const int td = qw >> 6;             // warp's diagonal kv-tile

    // load Q tile [64 q][64 d] (half, uint4 = 8 halves)
    #pragma unroll
    for (int i = 0; i < 4; i++) {
        int idx = tid + i*128;
        int q = idx >> 3, d8 = (idx & 7) << 3;
        *reinterpret_cast<uint4*>(&Qs[q*ATS + d8]) =
            *reinterpret_cast<const uint4*>(qkvh + (size_t)(b*Tc + q0 + q)*3*Cc + h*Dc + d8);
    }

    float o[8][4];
    #pragma unroll
    for (int i = 0; i < 8; i++)
        #pragma unroll
        for (int j = 0; j < 4; j++) o[i][j] = 0.f;
    float m0 = -1e30f, m1 = -1e30f, l0 = 0.f, l1 = 0.f;
    unsigned qa[4][4];
    bool qloaded = false;

    const int ntiles = (q0 >> 6) + 1;
    for (int t = 0; t < ntiles; t++) {
        __syncthreads();
        // load K,V tiles [64 s][64 d]
        #pragma unroll
        for (int i = 0; i < 4; i++) {
            int idx = tid + i*128;
            int s = idx >> 3, d8 = (idx & 7) << 3;
            const __half* base = qkvh + (size_t)(b*Tc + t*64 + s)*3*Cc + h*Dc + d8;
            *reinterpret_cast<uint4*>(&Ks[s*ATS + d8]) =
                *reinterpret_cast<const uint4*>(base + Cc);
            *reinterpret_cast<uint4*>(&Vs[s*ATS + d8]) =
                *reinterpret_cast<const uint4*>(base + 2*Cc);
        }
        __syncthreads();

        if (!qloaded) {
            #pragma unroll
            for (int kc = 0; kc < 4; kc++) {
                uint32_t addr = smem_u32(&Qs[(w*16 + (lane & 15))*ATS + kc*16 + ((lane >> 4) << 3)]);
                ldsm_x4(qa[kc][0], qa[kc][1], qa[kc][2], qa[kc][3], addr);
            }
            qloaded = true;
        }
        if (t > td) continue;           // fully masked for this warp (barriers already done)

        // ---- S = Q K^T : 8 n-tiles (s), 4 k-chunks (d) ----
        float sc[8][4];
        #pragma unroll
        for (int i = 0; i < 8; i++)
            #pragma unroll
            for (int j = 0; j < 4; j++) sc[i][j] = 0.f;
        #pragma unroll
        for (int kc = 0; kc < 4; kc++) {
            #pragma unroll
            for (int nt = 0; nt < 8; nt++) {
                unsigned b0, b1;
                uint32_t addr = smem_u32(&Ks[(nt*8 + (lane & 7))*ATS + kc*16 + (((lane >> 3) & 1) << 3)]);
                ldsm_x2(b0, b1, addr);
                mma_f16(sc[nt][0], sc[nt][1], sc[nt][2], sc[nt][3],
                        qa[kc][0], qa[kc][1], qa[kc][2], qa[kc][3], b0, b1);
            }
        }

        // ---- scale + causal mask ----
        const int qr0 = qw + (lane >> 2), qr1 = qr0 + 8;
        #pragma unroll
        for (int nt = 0; nt < 8; nt++) {
            int sb = t*64 + nt*8 + ((lane & 3) << 1);
            #pragma unroll
            for (int j = 0; j < 4; j++) sc[nt][j] *= 0.125f;
            if (t == td) {
                if (sb     > qr0) sc[nt][0] = -1e30f;
                if (sb + 1 > qr0) sc[nt][1] = -1e30f;
                if (sb     > qr1) sc[nt][2] = -1e30f;
                if (sb + 1 > qr1) sc[nt][3] = -1e30f;
            }
        }

        // ---- online softmax (rows qr0, qr1) ----
        float mx0 = -1e30f, mx1 = -1e30f;
        #pragma unroll
        for (int nt = 0; nt < 8; nt++) {
            mx0 = fmaxf(mx0, fmaxf(sc[nt][0], sc[nt][1]));
            mx1 = fmaxf(mx1, fmaxf(sc[nt][2], sc[nt][3]));
        }
        mx0 = fmaxf(mx0, __shfl_xor_sync(0xffffffffu, mx0, 1));
        mx0 = fmaxf(mx0, __shfl_xor_sync(0xffffffffu, mx0, 2));
        mx1 = fmaxf(mx1, __shfl_xor_sync(0xffffffffu, mx1, 1));
        mx1 = fmaxf(mx1, __shfl_xor_sync(0xffffffffu, mx1, 2));
        float mn0 = fmaxf(m0, mx0), mn1 = fmaxf(m1, mx1);
        float al0 = __expf(m0 - mn0), al1 = __expf(m1 - mn1);
        float ls0 = 0.f, ls1 = 0.f;
        #pragma unroll
        for (int nt = 0; nt < 8; nt++) {
            sc[nt][0] = __expf(sc[nt][0] - mn0);
            sc[nt][1] = __expf(sc[nt][1] - mn0);
            sc[nt][2] = __expf(sc[nt][2] - mn1);
            sc[nt][3] = __expf(sc[nt][3] - mn1);
            ls0 += sc[nt][0] + sc[nt][1];
            ls1 += sc[nt][2] + sc[nt][3];
        }
        ls0 += __shfl_xor_sync(0xffffffffu, ls0, 1);
        ls0 += __shfl_xor_sync(0xffffffffu, ls0, 2);
        ls1 += __shfl_xor_sync(0xffffffffu, ls1, 1);
        ls1 += __shfl_xor_sync(0xffffffffu, ls1, 2);
        l0 = l0*al0 + ls0;  m0 = mn0;
        l1 = l1*al1 + ls1;  m1 = mn1;
        #pragma unroll
        for (int nt = 0; nt < 8; nt++) {
            o[nt][0] *= al0; o[nt][1] *= al0;
            o[nt][2] *= al1; o[nt][3] *= al1;
        }

        // ---- P fragments (half) from S accumulators ----
        unsigned pa[4][4];
        #pragma unroll
        for (int kc = 0; kc < 4; kc++) {
            pa[kc][0] = pack_h2(sc[2*kc  ][0], sc[2*kc  ][1]);
            pa[kc][1] = pack_h2(sc[2*kc  ][2], sc[2*kc  ][3]);
            pa[kc][2] = pack_h2(sc[2*kc+1][0], sc[2*kc+1][1]);
            pa[kc][3] = pack_h2(sc[2*kc+1][2], sc[2*kc+1][3]);
        }

        // ---- O += P V : k = s (4 chunks of 16), n = d (8 tiles) ----
        #pragma unroll
        for (int kc = 0; kc < 4; kc++) {
            #pragma unroll
            for (int nt = 0; nt < 8; nt++) {
                unsigned b0, b1;
                uint32_t addr = smem_u32(&Vs[(kc*16 + (lane & 15))*ATS + nt*8]);
                ldsm_x2t(b0, b1, addr);
                mma_f16(o[nt][0], o[nt][1], o[nt][2], o[nt][3],
                        pa[kc][0], pa[kc][1], pa[kc][2], pa[kc][3], b0, b1);
            }
        }
    }

    // ---- write ----
    float inv0 = 1.0f / l0, inv1 = 1.0f / l1;
    const int qr0 = qw + (lane >> 2), qr1 = qr0 + 8;
    #pragma unroll
    for (int nt = 0; nt < 8; nt++) {
        int d = nt*8 + ((lane & 3) << 1);
        float* p0 = out + (size_t)(b*Tc + qr0)*Cc + h*Dc + d;
        float* p1 = out + (size_t)(b*Tc + qr1)*Cc + h*Dc + d;
        p0[0] = o[nt][0]*inv0; p0[1] = o[nt][1]*inv0;
        p1[0] = o[nt][2]*inv1; p1[1] = o[nt][3]*inv1;
    }
}

// -------------------- launch --------------------
extern "C" void kernel_launch(void* const* d_in, const int* in_sizes, int n_in,
                              void* d_out, int out_size) {
    const int*   idx       = (const int*)  d_in[0];
    const float* wte       = (const float*)d_in[1];
    const float* wpe       = (const float*)d_in[2];
    const float* ln1_w     = (const float*)d_in[3];
    const float* ln1_b     = (const float*)d_in[4];
    const float* attn_w    = (const float*)d_in[5];
    const float* attn_b    = (const float*)d_in[6];
    const float* proj_w    = (const float*)d_in[7];
    const float* proj_b    = (const float*)d_in[8];
    const float* ln2_w     = (const float*)d_in[9];
    const float* ln2_b     = (const float*)d_in[10];
    const float* fc_w      = (const float*)d_in[11];
    const float* fc_b      = (const float*)d_in[12];
    const float* fcproj_w  = (const float*)d_in[13];
    const float* fcproj_b  = (const float*)d_in[14];
    const float* lnf_w     = (const float*)d_in[15];
    const float* lnf_b     = (const float*)d_in[16];
    const float* lm_head_w = (const float*)d_in[17];
    float* out = (float*)d_out;

    float *x, *h, *att, *fc;
    __half *qkvh, *wqkv, *wproj, *wfc, *wfcp, *wlm;
    cudaGetSymbolAddress((void**)&x,    g_x);
    cudaGetSymbolAddress((void**)&h,    g_h);
    cudaGetSymbolAddress((void**)&att,  g_att);
    cudaGetSymbolAddress((void**)&fc,   g_fc);
    cudaGetSymbolAddress((void**)&qkvh, g_qkv_h);
    cudaGetSymbolAddress((void**)&wqkv, g_wqkv_h);
    cudaGetSymbolAddress((void**)&wproj,g_wproj_h);
    cudaGetSymbolAddress((void**)&wfc,  g_wfc_h);
    cudaGetSymbolAddress((void**)&wfcp, g_wfcp_h);
    cudaGetSymbolAddress((void**)&wlm,  g_wlm_h);

    // ---- convert weights to fp16 (padded) ----
    {
        int t1 = Lc*Cc*3*Cc;
        cvt_w_kernel<<<(t1+255)/256, 256>>>(attn_w, wqkv, t1, 3*Cc, 3*Cc);
        int t2 = Lc*Cc*Cc;
        cvt_w_kernel<<<(t2+255)/256, 256>>>(proj_w, wproj, t2, Cc, Cc);
        int t3 = Lc*Cc*4*Cc;
        cvt_w_kernel<<<(t3+255)/256, 256>>>(fc_w, wfc, t3, 4*Cc, 4*Cc);
        int t4 = Lc*4*Cc*Cc;
        cvt_w_kernel<<<(t4+255)/256, 256>>>(fcproj_w, wfcp, t4, Cc, Cc);
        int t5 = Cc*Vpad;
        cvt_w_kernel<<<(t5+255)/256, 256>>>(lm_head_w, wlm, t5, Vc, Vpad);
    }

    embed_kernel<<<(Mc*Cc + 255)/256, 256>>>(idx, wte, wpe);

    dim3 gQKV(3*Cc/128, Mc/128);
    dim3 gPROJ(Cc/128, Mc/128);
    dim3 gFC(4*Cc/128, Mc/128);
    dim3 gHEAD(Vpad/128, Mc/128);
    dim3 gATT(Tc/64, Hc, Bc);

    for (int l = 0; l < Lc; l++) {
        ln_kernel<<<Mc, 256>>>(x, h, ln1_w + l*Cc, ln1_b + l*Cc);
        gemm_hm<<<gQKV, 256>>>(h, wqkv + (size_t)l*Cc*3*Cc, 3*Cc,
                               attn_b + (size_t)l*3*Cc, nullptr,
                               nullptr, qkvh, Mc, 3*Cc, Cc, 0);
        attn_mma_kernel<<<gATT, 128>>>(qkvh, att);
        gemm_hm<<<gPROJ, 256>>>(att, wproj + (size_t)l*Cc*Cc, Cc,
                                proj_b + (size_t)l*Cc, x,
                                x, nullptr, Mc, Cc, Cc, 0);
        ln_kernel<<<Mc, 256>>>(x, h, ln2_w + l*Cc, ln2_b + l*Cc);
        gemm_hm<<<gFC, 256>>>(h, wfc + (size_t)l*Cc*4*Cc, 4*Cc,
                              fc_b + (size_t)l*4*Cc, nullptr,
                              fc, nullptr, Mc, 4*Cc, Cc, 1);
        gemm_hm<<<gPROJ, 256>>>(fc, wfcp + (size_t)l*4*Cc*Cc, Cc,
                                fcproj_b + (size_t)l*Cc, x,
                                x, nullptr, Mc, Cc, 4*Cc, 0);
    }

    ln_kernel<<<Mc, 256>>>(x, h, lnf_w, lnf_b);
    gemm_hm<<<gHEAD, 256>>>(h, wlm, Vpad, nullptr, nullptr,
                            out, nullptr, Mc, Vc, Cc, 0);
}

// round 15
// speedup vs baseline: 7.6030x; 1.0475x over previous
#include <cuda_runtime.h>
#include <cuda_fp16.h>
#include <math.h>
#include <stdint.h>

// GPT-2 small forward: B=2, T=1024, L=12, C=1024, H=16, D=64, V=50257
#define Bc 2
#define Tc 1024
#define Cc 1024
#define Hc 16
#define Dc 64
#define Lc 12
#define Vc 50257
#define Vpad 50304        // multiple of 128
#define Mc (Bc*Tc)        // 2048 tokens

// -------------------- scratch (device globals; no allocation) --------------------
__device__ float  g_x[Mc*Cc];          // residual stream (fp32)
__device__ __half g_h_h[Mc*Cc];        // layernorm output (fp16)
__device__ __half g_att_h[Mc*Cc];      // attention output (fp16)
__device__ __half g_fc_h[Mc*4*Cc];     // mlp hidden (fp16, post-gelu)
__device__ __half g_qkv_h[Mc*3*Cc];    // qkv (fp16)
// fp16 weights (converted once per launch)
__device__ __half g_wqkv_h[Lc*Cc*3*Cc];
__device__ __half g_wproj_h[Lc*Cc*Cc];
__device__ __half g_wfc_h[Lc*Cc*4*Cc];
__device__ __half g_wfcp_h[Lc*4*Cc*Cc];
__device__ __half g_wlm_h[Cc*Vpad];

// -------------------- helpers --------------------
__device__ __forceinline__ float gelu_f(float x) {
    const float k = 0.7978845608028654f;
    float x3 = x*x*x;
    return 0.5f*x*(1.0f + tanhf(k*(x + 0.044715f*x3)));
}
__device__ __forceinline__ uint32_t smem_u32(const void* p) {
    uint32_t a;
    asm("{ .reg .u64 t; cvta.to.shared.u64 t, %1; cvt.u32.u64 %0, t; }" : "=r"(a) : "l"(p));
    return a;
}
__device__ __forceinline__ unsigned pack_h2(float lo, float hi) {
    __half2 h = __floats2half2_rn(lo, hi);
    return *reinterpret_cast<unsigned*>(&h);
}

template<int NT>
__device__ __forceinline__ float blockSum(float v, float* red) {
    #pragma unroll
    for (int o = 16; o > 0; o >>= 1) v += __shfl_xor_sync(0xffffffffu, v, o);
    int w = threadIdx.x >> 5;
    if ((threadIdx.x & 31) == 0) red[w] = v;
    __syncthreads();
    if (threadIdx.x == 0) {
        float s = 0.f;
        #pragma unroll
        for (int i = 0; i < NT/32; i++) s += red[i];
        red[0] = s;
    }
    __syncthreads();
    float r = red[0];
    __syncthreads();
    return r;
}

// -------------------- weight conversion --------------------
// flat contiguous fp32 -> fp16, 8 elems/thread
__global__ void cvt_flat8(const float4* __restrict__ src, uint4* __restrict__ dst, int n8) {
    int i = blockIdx.x*256 + threadIdx.x;
    if (i >= n8) return;
    float4 a = src[2*i], b = src[2*i+1];
    uint4 o;
    o.x = pack_h2(a.x, a.y); o.y = pack_h2(a.z, a.w);
    o.z = pack_h2(b.x, b.y); o.w = pack_h2(b.z, b.w);
    dst[i] = o;
}
// padded lm_head: [Cc, Vc] -> [Cc, Vpad], 4 elems/thread
__global__ void cvt_pad4(const float* __restrict__ src, uint2* __restrict__ dst, int n4) {
    int i = blockIdx.x*256 + threadIdx.x;
    if (i >= n4) return;
    int base = i*4;
    int row = base / Vpad, n = base - row*Vpad;
    float v[4];
    #pragma unroll
    for (int j = 0; j < 4; j++) {
        int c = n + j;
        v[j] = (c < Vc) ? __ldg(src + (size_t)row*Vc + c) : 0.f;
    }
    uint2 o; o.x = pack_h2(v[0], v[1]); o.y = pack_h2(v[2], v[3]);
    dst[i] = o;
}

// -------------------- embedding --------------------
__global__ void embed_kernel(const int* __restrict__ idx,
                             const float* __restrict__ wte,
                             const float* __restrict__ wpe) {
    int i = blockIdx.x*blockDim.x + threadIdx.x;
    if (i >= Mc*Cc) return;
    int row = i / Cc, c = i - row*Cc;
    int t = row & (Tc-1);
    g_x[i] = wte[(size_t)idx[row]*Cc + c] + wpe[t*Cc + c];
}

// -------------------- layernorm: fp32 in -> fp16 out --------------------
__global__ void ln_kernel(const float* __restrict__ in, __half* __restrict__ out,
                          const float* __restrict__ w, const float* __restrict__ b) {
    __shared__ float red[8];
    int row = blockIdx.x;
    const float* xr = in + (size_t)row*Cc;
    float v[4];
    float s = 0.f;
    #pragma unroll
    for (int i = 0; i < 4; i++) { v[i] = xr[threadIdx.x + i*256]; s += v[i]; }
    s = blockSum<256>(s, red);
    float mean = s * (1.0f/Cc);
    float vs = 0.f;
    #pragma unroll
    for (int i = 0; i < 4; i++) { float d = v[i]-mean; vs += d*d; }
    vs = blockSum<256>(vs, red);
    float rstd = rsqrtf(vs*(1.0f/Cc) + 1e-5f);
    __half* orow = out + (size_t)row*Cc;
    #pragma unroll
    for (int i = 0; i < 4; i++) {
        int c = threadIdx.x + i*256;
        orow[c] = __float2half((v[i]-mean)*rstd*w[c] + b[c]);
    }
}

// ==================== fp16 GEMM: cp.async double-buffered ====================
// C[M,N] = A[M,K](half) @ B[K,N](half) (+bias)(gelu)(+resid)
// 128x128 tile, BK=32, 256 threads (8 warps 2x4), m16n8k16.
#define ASH 40     // A smem row stride (halves)
#define BSH 136    // B smem row stride (halves)

__device__ __forceinline__ void mma_f16(float& c0, float& c1, float& c2, float& c3,
                                        unsigned a0, unsigned a1, unsigned a2, unsigned a3,
                                        unsigned b0, unsigned b1) {
    asm volatile(
        "mma.sync.aligned.m16n8k16.row.col.f32.f16.f16.f32 "
        "{%0,%1,%2,%3},{%4,%5,%6,%7},{%8,%9},{%0,%1,%2,%3};"
        : "+f"(c0), "+f"(c1), "+f"(c2), "+f"(c3)
        : "r"(a0), "r"(a1), "r"(a2), "r"(a3), "r"(b0), "r"(b1));
}
__device__ __forceinline__ void ldsm_x4(unsigned& r0, unsigned& r1, unsigned& r2, unsigned& r3,
                                        uint32_t addr) {
    asm volatile("ldmatrix.sync.aligned.m8n8.x4.shared.b16 {%0,%1,%2,%3}, [%4];"
                 : "=r"(r0), "=r"(r1), "=r"(r2), "=r"(r3) : "r"(addr));
}
__device__ __forceinline__ void ldsm_x2(unsigned& r0, unsigned& r1, uint32_t addr) {
    asm volatile("ldmatrix.sync.aligned.m8n8.x2.shared.b16 {%0,%1}, [%2];"
                 : "=r"(r0), "=r"(r1) : "r"(addr));
}
__device__ __forceinline__ void ldsm_x2t(unsigned& r0, unsigned& r1, uint32_t addr) {
    asm volatile("ldmatrix.sync.aligned.m8n8.x2.trans.shared.b16 {%0,%1}, [%2];"
                 : "=r"(r0), "=r"(r1) : "r"(addr));
}

__global__ void __launch_bounds__(256, 2)
gemm_hh(const __half* __restrict__ A, int lda,
        const __half* __restrict__ Bh, int ldb,
        const float* __restrict__ bias, const float* __restrict__ resid,
        float* __restrict__ Cm, __half* __restrict__ Ch,
        int M, int N, int K, int do_gelu) {
    __shared__ __half As[2][128*ASH];
    __shared__ __half Bs[2][32*BSH];
    const int tid = threadIdx.x;
    const int lane = tid & 31, wid = tid >> 5;
    const int wm = wid >> 2, wn = wid & 3;
    const int bm = blockIdx.y*128, bn = blockIdx.x*128;

    auto loadTiles = [&](int k0, int s) {
        #pragma unroll
        for (int i = 0; i < 2; i++) {          // A: 128 rows x 4 16B-chunks
            int e = tid + i*256;
            int row = e >> 2, c = (e & 3) << 3;
            uint32_t dst = smem_u32(&As[s][row*ASH + c]);
            const __half* src = A + (size_t)(bm+row)*lda + k0 + c;
            asm volatile("cp.async.cg.shared.global [%0], [%1], 16;"
                         :: "r"(dst), "l"(src) : "memory");
        }
        #pragma unroll
        for (int i = 0; i < 2; i++) {          // B: 32 rows x 16 16B-chunks
            int e = tid + i*256;
            int row = e >> 4, c = (e & 15) << 3;
            uint32_t dst = smem_u32(&Bs[s][row*BSH + c]);
            const __half* src = Bh + (size_t)(k0+row)*ldb + bn + c;
            asm volatile("cp.async.cg.shared.global [%0], [%1], 16;"
                         :: "r"(dst), "l"(src) : "memory");
        }
        asm volatile("cp.async.commit_group;" ::: "memory");
    };

    float acc[4][4][4];
    #pragma unroll
    for (int i = 0; i < 4; i++)
        #pragma unroll
        for (int j = 0; j < 4; j++)
            #pragma unroll
            for (int r = 0; r < 4; r++) acc[i][j][r] = 0.f;

    loadTiles(0, 0);
    asm volatile("cp.async.wait_group 0;" ::: "memory");
    __syncthreads();

    const int a_lm_row = wm*64 + (lane & 15);
    const int a_lm_k   = (lane >> 4) << 3;
    const int b_lm_k   = lane & 15;
    const int b_lm_n   = wn*32;

    int buf = 0;
    for (int k0 = 0; k0 < K; k0 += 32) {
        const bool has_next = (k0 + 32 < K);
        if (has_next) loadTiles(k0 + 32, buf ^ 1);

        #pragma unroll
        for (int ks = 0; ks < 2; ks++) {
            unsigned a[4][4], b[4][2];
            #pragma unroll
            for (int mt = 0; mt < 4; mt++) {
                uint32_t addr = smem_u32(&As[buf][(a_lm_row + mt*16)*ASH + ks*16 + a_lm_k]);
                ldsm_x4(a[mt][0], a[mt][1], a[mt][2], a[mt][3], addr);
            }
            #pragma unroll
            for (int nt = 0; nt < 4; nt++) {
                uint32_t addr = smem_u32(&Bs[buf][(ks*16 + b_lm_k)*BSH + b_lm_n + nt*8]);
                ldsm_x2t(b[nt][0], b[nt][1], addr);
            }
            #pragma unroll
            for (int mt = 0; mt < 4; mt++)
                #pragma unroll
                for (int nt = 0; nt < 4; nt++)
                    mma_f16(acc[mt][nt][0], acc[mt][nt][1], acc[mt][nt][2], acc[mt][nt][3],
                            a[mt][0], a[mt][1], a[mt][2], a[mt][3],
                            b[nt][0], b[nt][1]);
        }
        if (has_next) {
            asm volatile("cp.async.wait_group 0;" ::: "memory");
            __syncthreads();
            buf ^= 1;
        }
    }

    const int r0 = bm + wm*64 + (lane >> 2);
    const int c0 = bn + wn*32 + ((lane & 3) << 1);
    #pragma unroll
    for (int mt = 0; mt < 4; mt++) {
        #pragma unroll
        for (int nt = 0; nt < 4; nt++) {
            int cc = c0 + nt*8;
            #pragma unroll
            for (int half = 0; half < 2; half++) {
                int r = r0 + mt*16 + half*8;
                #pragma unroll
                for (int j = 0; j < 2; j++) {
                    int c = cc + j;
                    if (c < N) {
                        float v = acc[mt][nt][half*2 + j];
                        if (bias) v += bias[c];
                        if (do_gelu) v = gelu_f(v);
                        size_t o = (size_t)r*N + c;
                        if (resid) v += resid[o];
                        if (Cm) Cm[o] = v;
                        if (Ch) Ch[o] = __float2half(v);
                    }
                }
            }
        }
    }
}

// ==================== fp16 tensor-core flash attention ====================
#define ATS 72

__global__ void __launch_bounds__(128)
attn_mma_kernel(const __half* __restrict__ qkvh, __half* __restrict__ outh) {
    __shared__ __half Qs[64*ATS];
    __shared__ __half Ks[64*ATS];
    __shared__ __half Vs[64*ATS];

    const int q0 = blockIdx.x * 64;
    const int h  = blockIdx.y;
    const int b  = blockIdx.z;
    const int tid = threadIdx.x;
    const int lane = tid & 31, w = tid >> 5;
    const int qw = q0 + w*16;
    const int td = qw >> 6;

    #pragma unroll
    for (int i = 0; i < 4; i++) {
        int idx = tid + i*128;
        int q = idx >> 3, d8 = (idx & 7) << 3;
        *reinterpret_cast<uint4*>(&Qs[q*ATS + d8]) =
            *reinterpret_cast<const uint4*>(qkvh + (size_t)(b*Tc + q0 + q)*3*Cc + h*Dc + d8);
    }

    float o[8][4];
    #pragma unroll
    for (int i = 0; i < 8; i++)
        #pragma unroll
        for (int j = 0; j < 4; j++) o[i][j] = 0.f;
    float m0 = -1e30f, m1 = -1e30f, l0 = 0.f, l1 = 0.f;
    unsigned qa[4][4];
    bool qloaded = false;

    const int ntiles = (q0 >> 6) + 1;
    for (int t = 0; t < ntiles; t++) {
        __syncthreads();
        #pragma unroll
        for (int i = 0; i < 4; i++) {
            int idx = tid + i*128;
            int s = idx >> 3, d8 = (idx & 7) << 3;
            const __half* base = qkvh + (size_t)(b*Tc + t*64 + s)*3*Cc + h*Dc + d8;
            *reinterpret_cast<uint4*>(&Ks[s*ATS + d8]) =
                *reinterpret_cast<const uint4*>(base + Cc);
            *reinterpret_cast<uint4*>(&Vs[s*ATS + d8]) =
                *reinterpret_cast<const uint4*>(base + 2*Cc);
        }
        __syncthreads();

        if (!qloaded) {
            #pragma unroll
            for (int kc = 0; kc < 4; kc++) {
                uint32_t addr = smem_u32(&Qs[(w*16 + (lane & 15))*ATS + kc*16 + ((lane >> 4) << 3)]);
                ldsm_x4(qa[kc][0], qa[kc][1], qa[kc][2], qa[kc][3], addr);
            }
            qloaded = true;
        }
        if (t > td) continue;

        float sc[8][4];
        #pragma unroll
        for (int i = 0; i < 8; i++)
            #pragma unroll
            for (int j = 0; j < 4; j++) sc[i][j] = 0.f;
        #pragma unroll
        for (int kc = 0; kc < 4; kc++) {
            #pragma unroll
            for (int nt = 0; nt < 8; nt++) {
                unsigned b0, b1;
                uint32_t addr = smem_u32(&Ks[(nt*8 + (lane & 7))*ATS + kc*16 + (((lane >> 3) & 1) << 3)]);
                ldsm_x2(b0, b1, addr);
                mma_f16(sc[nt][0], sc[nt][1], sc[nt][2], sc[nt][3],
                        qa[kc][0], qa[kc][1], qa[kc][2], qa[kc][3], b0, b1);
            }
        }

        const int qr0 = qw + (lane >> 2), qr1 = qr0 + 8;
        #pragma unroll
        for (int nt = 0; nt < 8; nt++) {
            int sb = t*64 + nt*8 + ((lane & 3) << 1);
            #pragma unroll
            for (int j = 0; j < 4; j++) sc[nt][j] *= 0.125f;
            if (t == td) {
                if (sb     > qr0) sc[nt][0] = -1e30f;
                if (sb + 1 > qr0) sc[nt][1] = -1e30f;
                if (sb     > qr1) sc[nt][2] = -1e30f;
                if (sb + 1 > qr1) sc[nt][3] = -1e30f;
            }
        }

        float mx0 = -1e30f, mx1 = -1e30f;
        #pragma unroll
        for (int nt = 0; nt < 8; nt++) {
            mx0 = fmaxf(mx0, fmaxf(sc[nt][0], sc[nt][1]));
            mx1 = fmaxf(mx1, fmaxf(sc[nt][2], sc[nt][3]));
        }
        mx0 = fmaxf(mx0, __shfl_xor_sync(0xffffffffu, mx0, 1));
        mx0 = fmaxf(mx0, __shfl_xor_sync(0xffffffffu, mx0, 2));
        mx1 = fmaxf(mx1, __shfl_xor_sync(0xffffffffu, mx1, 1));
        mx1 = fmaxf(mx1, __shfl_xor_sync(0xffffffffu, mx1, 2));
        float mn0 = fmaxf(m0, mx0), mn1 = fmaxf(m1, mx1);
        float al0 = __expf(m0 - mn0), al1 = __expf(m1 - mn1);
        float ls0 = 0.f, ls1 = 0.f;
        #pragma unroll
        for (int nt = 0; nt < 8; nt++) {
            sc[nt][0] = __expf(sc[nt][0] - mn0);
            sc[nt][1] = __expf(sc[nt][1] - mn0);
            sc[nt][2] = __expf(sc[nt][2] - mn1);
            sc[nt][3] = __expf(sc[nt][3] - mn1);
            ls0 += sc[nt][0] + sc[nt][1];
            ls1 += sc[nt][2] + sc[nt][3];
        }
        ls0 += __shfl_xor_sync(0xffffffffu, ls0, 1);
        ls0 += __shfl_xor_sync(0xffffffffu, ls0, 2);
        ls1 += __shfl_xor_sync(0xffffffffu, ls1, 1);
        ls1 += __shfl_xor_sync(0xffffffffu, ls1, 2);
        l0 = l0*al0 + ls0;  m0 = mn0;
        l1 = l1*al1 + ls1;  m1 = mn1;
        #pragma unroll
        for (int nt = 0; nt < 8; nt++) {
            o[nt][0] *= al0; o[nt][1] *= al0;
            o[nt][2] *= al1; o[nt][3] *= al1;
        }

        unsigned pa[4][4];
        #pragma unroll
        for (int kc = 0; kc < 4; kc++) {
            pa[kc][0] = pack_h2(sc[2*kc  ][0], sc[2*kc  ][1]);
            pa[kc][1] = pack_h2(sc[2*kc  ][2], sc[2*kc  ][3]);
            pa[kc][2] = pack_h2(sc[2*kc+1][0], sc[2*kc+1][1]);
            pa[kc][3] = pack_h2(sc[2*kc+1][2], sc[2*kc+1][3]);
        }

        #pragma unroll
        for (int kc = 0; kc < 4; kc++) {
            #pragma unroll
            for (int nt = 0; nt < 8; nt++) {
                unsigned b0, b1;
                uint32_t addr = smem_u32(&Vs[(kc*16 + (lane & 15))*ATS + nt*8]);
                ldsm_x2t(b0, b1, addr);
                mma_f16(o[nt][0], o[nt][1], o[nt][2], o[nt][3],
                        pa[kc][0], pa[kc][1], pa[kc][2], pa[kc][3], b0, b1);
            }
        }
    }

    float inv0 = 1.0f / l0, inv1 = 1.0f / l1;
    const int qr0 = qw + (lane >> 2), qr1 = qr0 + 8;
    #pragma unroll
    for (int nt = 0; nt < 8; nt++) {
        int d = nt*8 + ((lane & 3) << 1);
        __half* p0 = outh + (size_t)(b*Tc + qr0)*Cc + h*Dc + d;
        __half* p1 = outh + (size_t)(b*Tc + qr1)*Cc + h*Dc + d;
        *reinterpret_cast<__half2*>(p0) = __floats2half2_rn(o[nt][0]*inv0, o[nt][1]*inv0);
        *reinterpret_cast<__half2*>(p1) = __floats2half2_rn(o[nt][2]*inv1, o[nt][3]*inv1);
    }
}

// -------------------- launch --------------------
extern "C" void kernel_launch(void* const* d_in, const int* in_sizes, int n_in,
                              void* d_out, int out_size) {
    const int*   idx       = (const int*)  d_in[0];
    const float* wte       = (const float*)d_in[1];
    const float* wpe       = (const float*)d_in[2];
    const float* ln1_w     = (const float*)d_in[3];
    const float* ln1_b     = (const float*)d_in[4];
    const float* attn_w    = (const float*)d_in[5];
    const float* attn_b    = (const float*)d_in[6];
    const float* proj_w    = (const float*)d_in[7];
    const float* proj_b    = (const float*)d_in[8];
    const float* ln2_w     = (const float*)d_in[9];
    const float* ln2_b     = (const float*)d_in[10];
    const float* fc_w      = (const float*)d_in[11];
    const float* fc_b      = (const float*)d_in[12];
    const float* fcproj_w  = (const float*)d_in[13];
    const float* fcproj_b  = (const float*)d_in[14];
    const float* lnf_w     = (const float*)d_in[15];
    const float* lnf_b     = (const float*)d_in[16];
    const float* lm_head_w = (const float*)d_in[17];
    float* out = (float*)d_out;

    float *x;
    __half *hh, *atth, *fch, *qkvh, *wqkv, *wproj, *wfc, *wfcp, *wlm;
    cudaGetSymbolAddress((void**)&x,    g_x);
    cudaGetSymbolAddress((void**)&hh,   g_h_h);
    cudaGetSymbolAddress((void**)&atth, g_att_h);
    cudaGetSymbolAddress((void**)&fch,  g_fc_h);
    cudaGetSymbolAddress((void**)&qkvh, g_qkv_h);
    cudaGetSymbolAddress((void**)&wqkv, g_wqkv_h);
    cudaGetSymbolAddress((void**)&wproj,g_wproj_h);
    cudaGetSymbolAddress((void**)&wfc,  g_wfc_h);
    cudaGetSymbolAddress((void**)&wfcp, g_wfcp_h);
    cudaGetSymbolAddress((void**)&wlm,  g_wlm_h);

    // ---- convert weights to fp16 ----
    {
        int n1 = Lc*Cc*3*Cc/8;
        cvt_flat8<<<(n1+255)/256, 256>>>((const float4*)attn_w, (uint4*)wqkv, n1);
        int n2 = Lc*Cc*Cc/8;
        cvt_flat8<<<(n2+255)/256, 256>>>((const float4*)proj_w, (uint4*)wproj, n2);
        int n3 = Lc*Cc*4*Cc/8;
        cvt_flat8<<<(n3+255)/256, 256>>>((const float4*)fc_w, (uint4*)wfc, n3);
        int n4 = Lc*4*Cc*Cc/8;
        cvt_flat8<<<(n4+255)/256, 256>>>((const float4*)fcproj_w, (uint4*)wfcp, n4);
        int n5 = Cc*Vpad/4;
        cvt_pad4<<<(n5+255)/256, 256>>>(lm_head_w, (uint2*)wlm, n5);
    }

    embed_kernel<<<(Mc*Cc + 255)/256, 256>>>(idx, wte, wpe);

    dim3 gQKV(3*Cc/128, Mc/128);
    dim3 gPROJ(Cc/128, Mc/128);
    dim3 gFC(4*Cc/128, Mc/128);
    dim3 gHEAD(Vpad/128, Mc/128);
    dim3 gATT(Tc/64, Hc, Bc);

    for (int l = 0; l < Lc; l++) {
        ln_kernel<<<Mc, 256>>>(x, hh, ln1_w + l*Cc, ln1_b + l*Cc);
        gemm_hh<<<gQKV, 256>>>(hh, Cc, wqkv + (size_t)l*Cc*3*Cc, 3*Cc,
                               attn_b + (size_t)l*3*Cc, nullptr,
                               nullptr, qkvh, Mc, 3*Cc, Cc, 0);
        attn_mma_kernel<<<gATT, 128>>>(qkvh, atth);
        gemm_hh<<<gPROJ, 256>>>(atth, Cc, wproj + (size_t)l*Cc*Cc, Cc,
                                proj_b + (size_t)l*Cc, x,
                                x, nullptr, Mc, Cc, Cc, 0);
        ln_kernel<<<Mc, 256>>>(x, hh, ln2_w + l*Cc, ln2_b + l*Cc);
        gemm_hh<<<gFC, 256>>>(hh, Cc, wfc + (size_t)l*Cc*4*Cc, 4*Cc,
                              fc_b + (size_t)l*4*Cc, nullptr,
                              nullptr, fch, Mc, 4*Cc, Cc, 1);
        gemm_hh<<<gPROJ, 256>>>(fch, 4*Cc, wfcp + (size_t)l*4*Cc*Cc, Cc,
                                fcproj_b + (size_t)l*Cc, x,
                                x, nullptr, Mc, Cc, 4*Cc, 0);
    }

    ln_kernel<<<Mc, 256>>>(x, hh, lnf_w, lnf_b);
    gemm_hh<<<gHEAD, 256>>>(hh, Cc, wlm, Vpad, nullptr, nullptr,
                            out, nullptr, Mc, Vc, Cc, 0);
}